// round 11
// baseline (speedup 1.0000x reference)
#include <cuda_runtime.h>
#include <cstdint>
#include <cstddef>

// ---------------- problem constants ----------------
#define NTOT   100000
#define NPT    50000
#define NPG    50000
#define EG     500000
#define NG     4
#define NH     4
#define HD     64
#define HID    64
#define DD     256
#define OUTD   64
#define TT     20000

typedef unsigned long long u64;

// ---------------- device scratch (static, no allocs) ----------------
__device__ float g_transformed[(size_t)NTOT * HID];
__device__ float g_fcWt[2 * 256 * 64];        // fc_W transposed [ty][k][o] (fp32, no dup)
__device__ float g_z[(size_t)NG * NPG * DD];
__device__ float g_el[NG * NPG * NH];
__device__ float g_er[NG * NPG * NH];
__device__ int   g_cnt[NG * NPG];
__device__ int   g_cur[NG * NPG];
__device__ int   g_offs[NG * (NPG + 1)];
__device__ int   g_csr[NG * EG];
__device__ int   g_flag[NG * NPG];
__device__ int   g_list[NG * TT];
__device__ int   g_wcnt[NG];
__device__ float g_o[(size_t)NG * NPG * DD];
__device__ float g_wsum[NG];
__device__ float g_beta[NG];

__device__ __forceinline__ float lrelu(float x) { return fmaxf(x, 0.2f * x); }
__device__ __forceinline__ float tanh_fast(float x) {
    float y; asm("tanh.approx.f32 %0, %1;" : "=f"(y) : "f"(x)); return y;
}
__device__ __forceinline__ void fma2(u64& acc, u64 a, u64 b) {
    asm("fma.rn.f32x2 %0, %1, %2, %0;" : "+l"(acc) : "l"(a), "l"(b));
}
__device__ __forceinline__ u64 pack2(float x) {
    u64 d; asm("mov.b64 %0, {%1, %1};" : "=l"(d) : "f"(x)); return d;
}
__device__ __forceinline__ float2 unpack2(u64 v) {
    float2 r; asm("mov.b64 {%0, %1}, %2;" : "=f"(r.x), "=f"(r.y) : "l"(v)); return r;
}
__device__ __forceinline__ u64 add2(u64 a, u64 b) {
    u64 d; asm("add.rn.f32x2 %0, %1, %2;" : "=l"(d) : "l"(a), "l"(b)); return d;
}

// ---------------- transpose fc_W -> [ty][k][o] (tiny, fp32) ----------------
__global__ void k_tw(const float* __restrict__ fcW) {
    int i = blockIdx.x * blockDim.x + threadIdx.x;
    if (i < 2 * 256 * 64) {
        int ty = i >> 14, rem = i & 16383, k = rem >> 6, o = rem & 63;
        g_fcWt[i] = fcW[ty * 16384 + o * 256 + k];
    }
}

// ---------------- zero per-call scratch ----------------
__global__ void k_zero() {
    int i = blockIdx.x * blockDim.x + threadIdx.x;
    if (i < NG * NPG) { g_cnt[i] = 0; g_cur[i] = 0; g_flag[i] = 0; }
    if (i < NG) { g_wsum[i] = 0.f; g_wcnt[i] = 0; }
}

// ---------------- 1: type FC (20 rows/block, 160 thr, colpair) ----------------
// jt = t&15 -> cols jt*4 (2 colpairs); rg = t>>4 -> 2 rows
__global__ void k_fc(const float* __restrict__ f0, const float* __restrict__ f1,
                     const float* __restrict__ fcb, const int* __restrict__ type_idx) {
    int ty = blockIdx.y;
    int row0 = blockIdx.x * 20;
    __shared__ u64 sx2[256 * 22];             // dup (x,x), layout [k][r] pad 22
    int t = threadIdx.x;                      // 160
    const float* f = (ty == 0 ? f0 : f1);
    for (int i = t; i < 20 * 256; i += 160) {
        int r = i >> 8, k = i & 255;
        sx2[k * 22 + r] = pack2(f[(size_t)(row0 + r) * 256 + k]);
    }
    __syncthreads();
    int jt = t & 15, rg = t >> 4;
    const float* Wt = g_fcWt + ty * 16384 + jt * 4;
    u64 acc[2][2] = {};                       // [colpair][row]
    #pragma unroll 4
    for (int k = 0; k < 256; k++) {
        ulonglong2 w = *(const ulonglong2*)(Wt + k * 64);
        ulonglong2 x = *(const ulonglong2*)&sx2[k * 22 + rg * 2];
        fma2(acc[0][0], w.x, x.x); fma2(acc[1][0], w.y, x.x);
        fma2(acc[0][1], w.x, x.y); fma2(acc[1][1], w.y, x.y);
    }
    float4 bb = *(const float4*)(fcb + ty * 64 + jt * 4);
    #pragma unroll
    for (int p = 0; p < 2; p++) {
        float2 c0 = unpack2(acc[0][p]), c1 = unpack2(acc[1][p]);
        int row = row0 + rg * 2 + p;
        int d = type_idx[ty * NPT + row];
        *(float4*)(g_transformed + (size_t)d * 64 + jt * 4) =
            make_float4(c0.x + bb.x, c0.y + bb.y, c1.x + bb.z, c1.y + bb.w);
    }
}

// ---------------- 2: gather + z = h @ gat_W, fused el/er ----------------
// 40 rows/block, 320 thr: jt = t&63 (cols jt*4), rg = t>>6 (8 rows each)
__global__ void k_gatz(const float* __restrict__ gatW, const int* __restrict__ node_idx,
                       const float* __restrict__ al, const float* __restrict__ ar) {
    int g = blockIdx.y;
    int row0 = blockIdx.x * 40;
    __shared__ u64 sx2[64 * 42];              // dup (x,x), layout [k][r] pad 42
    int t = threadIdx.x;                      // 320
    for (int i = t; i < 40 * 64; i += 320) {
        int r = i >> 6, k = i & 63;
        int node = node_idx[g * NPG + row0 + r];
        sx2[k * 42 + r] = pack2(g_transformed[(size_t)node * 64 + k]);
    }
    __syncthreads();
    int jt = t & 63, rg = t >> 6;             // rg 0..4, rows rg*8..rg*8+7
    const float* W = gatW + (size_t)g * 16384 + jt * 4;
    u64 acc[2][8] = {};                       // [colpair][row]
    #pragma unroll 2
    for (int k = 0; k < 64; k++) {
        ulonglong2 w  = *(const ulonglong2*)(W + k * 256);
        const u64* xs = &sx2[k * 42 + rg * 8];
        ulonglong2 xa = *(const ulonglong2*)(xs);
        ulonglong2 xb = *(const ulonglong2*)(xs + 2);
        ulonglong2 xc = *(const ulonglong2*)(xs + 4);
        ulonglong2 xd = *(const ulonglong2*)(xs + 6);
        fma2(acc[0][0], w.x, xa.x); fma2(acc[1][0], w.y, xa.x);
        fma2(acc[0][1], w.x, xa.y); fma2(acc[1][1], w.y, xa.y);
        fma2(acc[0][2], w.x, xb.x); fma2(acc[1][2], w.y, xb.x);
        fma2(acc[0][3], w.x, xb.y); fma2(acc[1][3], w.y, xb.y);
        fma2(acc[0][4], w.x, xc.x); fma2(acc[1][4], w.y, xc.x);
        fma2(acc[0][5], w.x, xc.y); fma2(acc[1][5], w.y, xc.y);
        fma2(acc[0][6], w.x, xd.x); fma2(acc[1][6], w.y, xd.x);
        fma2(acc[0][7], w.x, xd.y); fma2(acc[1][7], w.y, xd.y);
    }
    ulonglong2 alp = *(const ulonglong2*)(al + g * DD + jt * 4);
    ulonglong2 arp = *(const ulonglong2*)(ar + g * DD + jt * 4);
    int h = jt >> 4;
    #pragma unroll
    for (int p = 0; p < 8; p++) {
        float2 c0 = unpack2(acc[0][p]), c1 = unpack2(acc[1][p]);
        int row = row0 + rg * 8 + p;
        *(float4*)(g_z + ((size_t)g * NPG + row) * DD + jt * 4) =
            make_float4(c0.x, c0.y, c1.x, c1.y);
        u64 sl = 0, sr = 0;
        fma2(sl, acc[0][p], alp.x); fma2(sl, acc[1][p], alp.y);
        fma2(sr, acc[0][p], arp.x); fma2(sr, acc[1][p], arp.y);
        #pragma unroll
        for (int off = 1; off < 16; off <<= 1) {
            sl = add2(sl, __shfl_xor_sync(~0u, sl, off));
            sr = add2(sr, __shfl_xor_sync(~0u, sr, off));
        }
        if ((jt & 15) == 0) {
            float2 a = unpack2(sl), c = unpack2(sr);
            g_el[((size_t)g * NPG + row) * NH + h] = a.x + a.y;
            g_er[((size_t)g * NPG + row) * NH + h] = c.x + c.y;
        }
    }
}

// ---------------- 3: CSR build ----------------
__global__ void k_count(const int* __restrict__ edst) {
    int i = blockIdx.x * blockDim.x + threadIdx.x;
    if (i < NG * EG) { int g = i / EG; atomicAdd(&g_cnt[g * NPG + edst[i]], 1); }
}

__global__ void k_scan() {
    int g = blockIdx.x;
    __shared__ int ssum[1024];
    int t = threadIdx.x;
    const int per = (NPG + 1023) / 1024;
    int beg = t * per, end = min(beg + per, NPG);
    int s = 0;
    for (int i = beg; i < end; i++) s += g_cnt[g * NPG + i];
    ssum[t] = s;
    __syncthreads();
    for (int off = 1; off < 1024; off <<= 1) {
        int v = (t >= off) ? ssum[t - off] : 0;
        __syncthreads();
        ssum[t] += v;
        __syncthreads();
    }
    int run = (t == 0) ? 0 : ssum[t - 1];
    for (int i = beg; i < end; i++) { g_offs[g * (NPG + 1) + i] = run; run += g_cnt[g * NPG + i]; }
    if (t == 1023) g_offs[g * (NPG + 1) + NPG] = run;
}

__global__ void k_scatter(const int* __restrict__ esrc, const int* __restrict__ edst) {
    int i = blockIdx.x * blockDim.x + threadIdx.x;
    if (i < NG * EG) {
        int g = i / EG;
        int d = edst[i];
        int pos = g_offs[g * (NPG + 1) + d] + atomicAdd(&g_cur[g * NPG + d], 1);
        g_csr[g * EG + pos] = esrc[i];
    }
}

__global__ void k_flag(const int* __restrict__ tgt) {
    int i = blockIdx.x * blockDim.x + threadIdx.x;
    if (i < NG * TT) {
        int g = i / TT;
        int d = tgt[i];
        if (atomicExch(&g_flag[g * NPG + d], 1) == 0) {
            int p = atomicAdd(&g_wcnt[g], 1);
            g_list[g * TT + p] = d;
        }
    }
}

// ---------------- 4: single-pass edge softmax + aggregation ----------------
__global__ void k_agg() {
    int g = blockIdx.y;
    int widx = blockIdx.x * 8 + (threadIdx.x >> 5);
    if (widx >= g_wcnt[g]) return;
    int lane = threadIdx.x & 31;
    int half = lane >> 4;
    int sub  = lane & 15;
    int h    = sub >> 2;
    int dst  = g_list[g * TT + widx];
    int beg = g_offs[g * (NPG + 1) + dst];
    int end = g_offs[g * (NPG + 1) + dst + 1];
    const int*   csr = g_csr + g * EG;
    const float* elg = g_el + (size_t)g * NPG * NH;
    const float* zg  = g_z + (size_t)g * NPG * DD;
    float erh = g_er[(g * NPG + dst) * NH + h];
    float acc[16] = {};
    float denom = 0.f;
    for (int i = beg + half; i < end; i += 2) {
        int src = csr[i];
        float e  = lrelu(elg[src * NH + h] + erh);
        float ex = __expf(e);
        denom += ex;
        const float4* zp = (const float4*)(zg + (size_t)src * DD + sub * 16);
        float4 a = zp[0], b = zp[1], c = zp[2], d = zp[3];
        acc[0]  += ex * a.x; acc[1]  += ex * a.y; acc[2]  += ex * a.z; acc[3]  += ex * a.w;
        acc[4]  += ex * b.x; acc[5]  += ex * b.y; acc[6]  += ex * b.z; acc[7]  += ex * b.w;
        acc[8]  += ex * c.x; acc[9]  += ex * c.y; acc[10] += ex * c.z; acc[11] += ex * c.w;
        acc[12] += ex * d.x; acc[13] += ex * d.y; acc[14] += ex * d.z; acc[15] += ex * d.w;
    }
    denom += __shfl_xor_sync(~0u, denom, 16);
    #pragma unroll
    for (int j = 0; j < 16; j++) acc[j] += __shfl_xor_sync(~0u, acc[j], 16);
    if (half == 0) {
        float inv = 1.f / (denom + 1e-9f);
        float* op = g_o + ((size_t)g * NPG + dst) * DD + sub * 16;
        float4 v[4];
        #pragma unroll
        for (int j = 0; j < 16; j++) {
            float x = acc[j] * inv;
            ((float*)v)[j] = (x > 0.f) ? x : (__expf(x) - 1.f);
        }
        #pragma unroll
        for (int j = 0; j < 4; j++) ((float4*)op)[j] = v[j];
    }
}

// ---------------- 5: semantic score (40 rows/block, 320 thr, colpair) ----------------
__global__ void k_sem(const float* __restrict__ semW, const float* __restrict__ semb,
                      const float* __restrict__ semq, const int* __restrict__ tgt) {
    extern __shared__ u64 sx2[];              // [256][42] dup
    __shared__ float sred[512];
    int g = blockIdx.y, b = g >> 1;
    int row0 = blockIdx.x * 40;
    int t = threadIdx.x;                      // 320
    for (int i = t; i < 40 * 256; i += 320) {
        int r = i >> 8, k = i & 255;
        int node = tgt[g * TT + row0 + r];
        sx2[k * 42 + r] = pack2(g_o[((size_t)g * NPG + node) * DD + k]);
    }
    __syncthreads();
    int jt = t & 63, rg = t >> 6;             // rg 0..4, 8 rows each
    const float* W = semW + (size_t)b * 65536 + jt * 4;
    u64 acc[2][8] = {};
    #pragma unroll 2
    for (int k = 0; k < 256; k++) {
        ulonglong2 w  = *(const ulonglong2*)(W + (size_t)k * 256);
        const u64* xs = &sx2[k * 42 + rg * 8];
        ulonglong2 xa = *(const ulonglong2*)(xs);
        ulonglong2 xb = *(const ulonglong2*)(xs + 2);
        ulonglong2 xc = *(const ulonglong2*)(xs + 4);
        ulonglong2 xd = *(const ulonglong2*)(xs + 6);
        fma2(acc[0][0], w.x, xa.x); fma2(acc[1][0], w.y, xa.x);
        fma2(acc[0][1], w.x, xa.y); fma2(acc[1][1], w.y, xa.y);
        fma2(acc[0][2], w.x, xb.x); fma2(acc[1][2], w.y, xb.x);
        fma2(acc[0][3], w.x, xb.y); fma2(acc[1][3], w.y, xb.y);
        fma2(acc[0][4], w.x, xc.x); fma2(acc[1][4], w.y, xc.x);
        fma2(acc[0][5], w.x, xc.y); fma2(acc[1][5], w.y, xc.y);
        fma2(acc[0][6], w.x, xd.x); fma2(acc[1][6], w.y, xd.x);
        fma2(acc[0][7], w.x, xd.y); fma2(acc[1][7], w.y, xd.y);
    }
    float4 bb = *(const float4*)(semb + b * DD + jt * 4);
    float4 qq = *(const float4*)(semq + b * DD + jt * 4);
    float part = 0.f;
    #pragma unroll
    for (int p = 0; p < 8; p++) {
        float2 c0 = unpack2(acc[0][p]), c1 = unpack2(acc[1][p]);
        part += tanh_fast(c0.x + bb.x) * qq.x + tanh_fast(c0.y + bb.y) * qq.y
              + tanh_fast(c1.x + bb.z) * qq.z + tanh_fast(c1.y + bb.w) * qq.w;
    }
    sred[t] = part;
    if (t < 192) sred[320 + t] = 0.f;
    __syncthreads();
    for (int s2 = 256; s2; s2 >>= 1) {
        if (t < s2) sred[t] += sred[t + s2];
        __syncthreads();
    }
    if (t == 0) atomicAdd(&g_wsum[g], sred[0]);
}

__global__ void k_beta() {
    if (threadIdx.x == 0 && blockIdx.x == 0) {
        for (int b = 0; b < 2; b++) {
            float w0 = g_wsum[b * 2 + 0] / (float)TT;
            float w1 = g_wsum[b * 2 + 1] / (float)TT;
            float mx = fmaxf(w0, w1);
            float e0 = __expf(w0 - mx), e1 = __expf(w1 - mx);
            float s = e0 + e1;
            g_beta[b * 2 + 0] = e0 / s;
            g_beta[b * 2 + 1] = e1 / s;
        }
    }
}

// ---------------- 6: beta-mix + fcout (20 rows/block, 160 thr, colpair) ----------------
__global__ void k_out(const float* __restrict__ foW, const float* __restrict__ fob,
                      const int* __restrict__ tgt, float* __restrict__ out) {
    int b = blockIdx.y;
    int row0 = blockIdx.x * 20;
    __shared__ u64 sx2[256 * 22];
    int t = threadIdx.x;                      // 160
    float b0 = g_beta[b * 2], b1 = g_beta[b * 2 + 1];
    for (int i = t; i < 20 * 256; i += 160) {
        int r = i >> 8, k = i & 255;
        int row = row0 + r;
        int n0 = tgt[(b * 2 + 0) * TT + row];
        int n1 = tgt[(b * 2 + 1) * TT + row];
        float v = b0 * g_o[((size_t)(b * 2 + 0) * NPG + n0) * DD + k]
                + b1 * g_o[((size_t)(b * 2 + 1) * NPG + n1) * DD + k];
        sx2[k * 22 + r] = pack2(v);
    }
    __syncthreads();
    int jt = t & 15, rg = t >> 4;             // 2 rows each
    const float* W = foW + (size_t)b * 16384 + jt * 4;   // natural [k][o]
    u64 acc[2][2] = {};
    #pragma unroll 4
    for (int k = 0; k < 256; k++) {
        ulonglong2 w = *(const ulonglong2*)(W + k * 64);
        ulonglong2 x = *(const ulonglong2*)&sx2[k * 22 + rg * 2];
        fma2(acc[0][0], w.x, x.x); fma2(acc[1][0], w.y, x.x);
        fma2(acc[0][1], w.x, x.y); fma2(acc[1][1], w.y, x.y);
    }
    float4 bb = *(const float4*)(fob + b * 64 + jt * 4);
    #pragma unroll
    for (int p = 0; p < 2; p++) {
        float2 c0 = unpack2(acc[0][p]), c1 = unpack2(acc[1][p]);
        int row = row0 + rg * 2 + p;
        *(float4*)(out + ((size_t)b * TT + row) * OUTD + jt * 4) =
            make_float4(c0.x + bb.x, c0.y + bb.y, c1.x + bb.z, c1.y + bb.w);
    }
}

// ---------------- launch ----------------
extern "C" void kernel_launch(void* const* d_in, const int* in_sizes, int n_in,
                              void* d_out, int out_size) {
    const float* features0 = (const float*)d_in[0];
    const float* features1 = (const float*)d_in[1];
    const float* fc_W      = (const float*)d_in[2];
    const float* fc_b      = (const float*)d_in[3];
    const float* gat_W     = (const float*)d_in[4];
    const float* attn_l    = (const float*)d_in[5];
    const float* attn_r    = (const float*)d_in[6];
    const float* sem_W     = (const float*)d_in[7];
    const float* sem_b     = (const float*)d_in[8];
    const float* sem_q     = (const float*)d_in[9];
    const float* fcout_W   = (const float*)d_in[10];
    const float* fcout_b   = (const float*)d_in[11];
    const int*   type_idx  = (const int*)d_in[12];
    const int*   node_idx  = (const int*)d_in[13];
    const int*   edge_src  = (const int*)d_in[14];
    const int*   edge_dst  = (const int*)d_in[15];
    const int*   tgt_idx   = (const int*)d_in[16];
    float* out = (float*)d_out;

    // unconditional, host-side, graph-capture-safe
    cudaFuncSetAttribute(k_sem, cudaFuncAttributeMaxDynamicSharedMemorySize,
                         256 * 42 * (int)sizeof(u64));

    k_tw<<<128, 256>>>(fc_W);                                   // 1
    k_zero<<<(NG * NPG + 255) / 256, 256>>>();                  // 2
    {
        dim3 grid(NPT / 20, 2);
        k_fc<<<grid, 160>>>(features0, features1, fc_b, type_idx);  // 3
    }
    {
        dim3 grid(NPG / 40, NG);
        k_gatz<<<grid, 320>>>(gat_W, node_idx, attn_l, attn_r); // 4 <- ncu capture slot
    }
    k_count<<<(NG * EG + 255) / 256, 256>>>(edge_dst);
    k_scan<<<NG, 1024>>>();
    k_scatter<<<(NG * EG + 255) / 256, 256>>>(edge_src, edge_dst);
    k_flag<<<(NG * TT + 255) / 256, 256>>>(tgt_idx);
    {
        dim3 grid((TT + 7) / 8, NG);
        k_agg<<<grid, 256>>>();
    }
    {
        dim3 grid(TT / 40, NG);
        k_sem<<<grid, 320, 256 * 42 * (int)sizeof(u64)>>>(sem_W, sem_b, sem_q, tgt_idx);
    }
    k_beta<<<1, 32>>>();
    {
        dim3 grid(TT / 20, 2);
        k_out<<<grid, 160>>>(fcout_W, fcout_b, tgt_idx, out);
    }
}

// round 12
// speedup vs baseline: 2.0516x; 2.0516x over previous
#include <cuda_runtime.h>
#include <cuda_bf16.h>
#include <cstdint>
#include <cstddef>

// ---------------- problem constants ----------------
#define NTOT   100000
#define NPT    50000
#define NPG    50000
#define EG     500000
#define NG     4
#define NH     4
#define HD     64
#define HID    64
#define DD     256
#define OUTD   64
#define TT     20000

typedef unsigned long long u64;

// ---------------- device scratch (static, no allocs) ----------------
__device__ float g_transformed[(size_t)NTOT * HID];
__device__ float g_fcWt[2 * 256 * 64];                 // fc_W transposed [ty][k][o]
__device__ __nv_bfloat16 g_semWbt[2 * 256 * 256];      // sem_W bf16 transposed [b][n][k]
__device__ float g_z[(size_t)NG * NPG * DD];
__device__ float g_el[NG * NPG * NH];
__device__ float g_er[NG * NPG * NH];
__device__ int   g_cnt[NG * NPG];
__device__ int   g_cur[NG * NPG];
__device__ int   g_offs[NG * (NPG + 1)];
__device__ int   g_csr[NG * EG];
__device__ int   g_flag[NG * NPG];
__device__ int   g_list[NG * TT];
__device__ int   g_wcnt[NG];
__device__ float g_o[(size_t)NG * NPG * DD];
__device__ float g_wsum[NG];
__device__ float g_beta[NG];

__device__ __forceinline__ float lrelu(float x) { return fmaxf(x, 0.2f * x); }
__device__ __forceinline__ float tanh_fast(float x) {
    float y; asm("tanh.approx.f32 %0, %1;" : "=f"(y) : "f"(x)); return y;
}
__device__ __forceinline__ void fma2(u64& acc, u64 a, u64 b) {
    asm("fma.rn.f32x2 %0, %1, %2, %0;" : "+l"(acc) : "l"(a), "l"(b));
}
__device__ __forceinline__ float2 unpack2(u64 v) {
    float2 r; asm("mov.b64 {%0, %1}, %2;" : "=f"(r.x), "=f"(r.y) : "l"(v)); return r;
}
__device__ __forceinline__ u64 add2(u64 a, u64 b) {
    u64 d; asm("add.rn.f32x2 %0, %1, %2;" : "=l"(d) : "l"(a), "l"(b)); return d;
}
// pack (lo,hi) floats into bf16x2 (lo = element 0)
__device__ __forceinline__ uint32_t bf2(float lo, float hi) {
    uint32_t r; asm("cvt.rn.bf16x2.f32 %0, %1, %2;" : "=r"(r) : "f"(hi), "f"(lo)); return r;
}
__device__ __forceinline__ void mma_bf16(float& c0, float& c1, float& c2, float& c3,
                                         uint32_t a0, uint32_t a1, uint32_t a2, uint32_t a3,
                                         uint32_t b0, uint32_t b1) {
    asm("mma.sync.aligned.m16n8k16.row.col.f32.bf16.bf16.f32 "
        "{%0,%1,%2,%3},{%4,%5,%6,%7},{%8,%9},{%0,%1,%2,%3};"
        : "+f"(c0), "+f"(c1), "+f"(c2), "+f"(c3)
        : "r"(a0), "r"(a1), "r"(a2), "r"(a3), "r"(b0), "r"(b1));
}

// ---------------- weight prep: fc_W transpose + sem_W bf16 transpose ----------------
__global__ void k_tw(const float* __restrict__ fcW, const float* __restrict__ semW) {
    int i = blockIdx.x * blockDim.x + threadIdx.x;
    if (i < 2 * 256 * 64) {                    // fcWt [ty][k][o]
        int ty = i >> 14, rem = i & 16383, k = rem >> 6, o = rem & 63;
        g_fcWt[i] = fcW[ty * 16384 + o * 256 + k];
    }
    int j = i - 2 * 256 * 64;
    if (j >= 0 && j < 2 * 256 * 256) {         // semWbt [b][n][k] <- semW [b][k][n]
        int b = j >> 16, rem = j & 65535, n = rem >> 8, k = rem & 255;
        g_semWbt[j] = __float2bfloat16(semW[b * 65536 + k * 256 + n]);
    }
}

// ---------------- zero per-call scratch ----------------
__global__ void k_zero() {
    int i = blockIdx.x * blockDim.x + threadIdx.x;
    if (i < NG * NPG) { g_cnt[i] = 0; g_cur[i] = 0; g_flag[i] = 0; }
    if (i < NG) { g_wsum[i] = 0.f; g_wcnt[i] = 0; }
}

// ---------------- 1: type FC (16 rows/block, 128 thr)  [R6 verbatim] ----------------
__global__ void k_fc(const float* __restrict__ f0, const float* __restrict__ f1,
                     const float* __restrict__ fcb, const int* __restrict__ type_idx) {
    int ty = blockIdx.y;
    int row0 = blockIdx.x * 16;
    __shared__ float sx[256 * 18];
    int t = threadIdx.x;                      // 128
    const float* f = (ty == 0 ? f0 : f1);
    for (int i = t; i < 16 * 256; i += 128) {
        int r = i >> 8, k = i & 255;
        sx[k * 18 + r] = f[(size_t)(row0 + r) * 256 + k];
    }
    __syncthreads();
    int oq = t & 15, rg = t >> 4;
    const float* Wt = g_fcWt + ty * 16384;
    u64 acc0 = 0, acc1 = 0, acc2 = 0, acc3 = 0;
    #pragma unroll 4
    for (int k = 0; k < 256; k++) {
        float4 w = *(const float4*)(Wt + k * 64 + oq * 4);
        u64 xp = *(const u64*)&sx[k * 18 + rg * 2];
        u64 w0, w1, w2, w3;
        asm("mov.b64 %0, {%1, %1};" : "=l"(w0) : "f"(w.x));
        asm("mov.b64 %0, {%1, %1};" : "=l"(w1) : "f"(w.y));
        asm("mov.b64 %0, {%1, %1};" : "=l"(w2) : "f"(w.z));
        asm("mov.b64 %0, {%1, %1};" : "=l"(w3) : "f"(w.w));
        fma2(acc0, w0, xp); fma2(acc1, w1, xp);
        fma2(acc2, w2, xp); fma2(acc3, w3, xp);
    }
    float4 bb = *(const float4*)(fcb + ty * 64 + oq * 4);
    float2 a0 = unpack2(acc0), a1 = unpack2(acc1), a2 = unpack2(acc2), a3 = unpack2(acc3);
    int r0 = row0 + rg * 2;
    int d0 = type_idx[ty * NPT + r0];
    int d1 = type_idx[ty * NPT + r0 + 1];
    *(float4*)(g_transformed + (size_t)d0 * 64 + oq * 4) =
        make_float4(a0.x + bb.x, a1.x + bb.y, a2.x + bb.z, a3.x + bb.w);
    *(float4*)(g_transformed + (size_t)d1 * 64 + oq * 4) =
        make_float4(a0.y + bb.x, a1.y + bb.y, a2.y + bb.z, a3.y + bb.w);
}

// ---------------- 2: gather + z = h @ gat_W, fused el/er (16 rows/block) [R6 verbatim] ----------------
__global__ void k_gatz(const float* __restrict__ gatW, const int* __restrict__ node_idx,
                       const float* __restrict__ al, const float* __restrict__ ar) {
    int g = blockIdx.y;
    int row0 = blockIdx.x * 16;
    __shared__ float sx[64 * 20];
    int t = threadIdx.x;                      // 256
    for (int i = t; i < 16 * 64; i += 256) {
        int r = i >> 6, k = i & 63;
        int node = node_idx[g * NPG + row0 + r];
        sx[k * 20 + r] = g_transformed[(size_t)node * 64 + k];
    }
    __syncthreads();
    int jt = t & 63, rg = t >> 6;
    const float* W = gatW + (size_t)g * 64 * 256;
    u64 a01[4] = {}, a23[4] = {};
    #pragma unroll 4
    for (int k = 0; k < 64; k++) {
        float4 w = *(const float4*)(W + k * 256 + jt * 4);
        ulonglong2 xp = *(const ulonglong2*)&sx[k * 20 + rg * 4];
        u64 w0, w1, w2, w3;
        asm("mov.b64 %0, {%1, %1};" : "=l"(w0) : "f"(w.x));
        asm("mov.b64 %0, {%1, %1};" : "=l"(w1) : "f"(w.y));
        asm("mov.b64 %0, {%1, %1};" : "=l"(w2) : "f"(w.z));
        asm("mov.b64 %0, {%1, %1};" : "=l"(w3) : "f"(w.w));
        fma2(a01[0], w0, xp.x); fma2(a01[1], w1, xp.x);
        fma2(a01[2], w2, xp.x); fma2(a01[3], w3, xp.x);
        fma2(a23[0], w0, xp.y); fma2(a23[1], w1, xp.y);
        fma2(a23[2], w2, xp.y); fma2(a23[3], w3, xp.y);
    }
    float2 u0 = unpack2(a01[0]), u1 = unpack2(a01[1]), u2 = unpack2(a01[2]), u3 = unpack2(a01[3]);
    float2 v0 = unpack2(a23[0]), v1 = unpack2(a23[1]), v2 = unpack2(a23[2]), v3 = unpack2(a23[3]);
    size_t zb = ((size_t)g * NPG + row0 + rg * 4) * DD + jt * 4;
    *(float4*)(g_z + zb)            = make_float4(u0.x, u1.x, u2.x, u3.x);
    *(float4*)(g_z + zb + DD)       = make_float4(u0.y, u1.y, u2.y, u3.y);
    *(float4*)(g_z + zb + 2 * DD)   = make_float4(v0.x, v1.x, v2.x, v3.x);
    *(float4*)(g_z + zb + 3 * DD)   = make_float4(v0.y, v1.y, v2.y, v3.y);
    float4 alv = *(const float4*)(al + g * DD + jt * 4);
    float4 arv = *(const float4*)(ar + g * DD + jt * 4);
    u64 aL0, aL1, aL2, aL3, aR0, aR1, aR2, aR3;
    asm("mov.b64 %0, {%1, %1};" : "=l"(aL0) : "f"(alv.x));
    asm("mov.b64 %0, {%1, %1};" : "=l"(aL1) : "f"(alv.y));
    asm("mov.b64 %0, {%1, %1};" : "=l"(aL2) : "f"(alv.z));
    asm("mov.b64 %0, {%1, %1};" : "=l"(aL3) : "f"(alv.w));
    asm("mov.b64 %0, {%1, %1};" : "=l"(aR0) : "f"(arv.x));
    asm("mov.b64 %0, {%1, %1};" : "=l"(aR1) : "f"(arv.y));
    asm("mov.b64 %0, {%1, %1};" : "=l"(aR2) : "f"(arv.z));
    asm("mov.b64 %0, {%1, %1};" : "=l"(aR3) : "f"(arv.w));
    u64 pl01 = 0, pl23 = 0, pr01 = 0, pr23 = 0;
    fma2(pl01, aL0, a01[0]); fma2(pl01, aL1, a01[1]);
    fma2(pl01, aL2, a01[2]); fma2(pl01, aL3, a01[3]);
    fma2(pl23, aL0, a23[0]); fma2(pl23, aL1, a23[1]);
    fma2(pl23, aL2, a23[2]); fma2(pl23, aL3, a23[3]);
    fma2(pr01, aR0, a01[0]); fma2(pr01, aR1, a01[1]);
    fma2(pr01, aR2, a01[2]); fma2(pr01, aR3, a01[3]);
    fma2(pr23, aR0, a23[0]); fma2(pr23, aR1, a23[1]);
    fma2(pr23, aR2, a23[2]); fma2(pr23, aR3, a23[3]);
    #pragma unroll
    for (int off = 1; off < 16; off <<= 1) {
        pl01 = add2(pl01, __shfl_xor_sync(~0u, pl01, off));
        pl23 = add2(pl23, __shfl_xor_sync(~0u, pl23, off));
        pr01 = add2(pr01, __shfl_xor_sync(~0u, pr01, off));
        pr23 = add2(pr23, __shfl_xor_sync(~0u, pr23, off));
    }
    if ((jt & 15) == 0) {
        int h = jt >> 4;
        int base = (g * NPG + row0 + rg * 4) * NH;
        float2 p0 = unpack2(pl01), p1 = unpack2(pl23);
        float2 q0 = unpack2(pr01), q1 = unpack2(pr23);
        g_el[base + h]           = p0.x;  g_er[base + h]           = q0.x;
        g_el[base + NH + h]      = p0.y;  g_er[base + NH + h]      = q0.y;
        g_el[base + 2 * NH + h]  = p1.x;  g_er[base + 2 * NH + h]  = q1.x;
        g_el[base + 3 * NH + h]  = p1.y;  g_er[base + 3 * NH + h]  = q1.y;
    }
}

// ---------------- 3: CSR build  [R6 verbatim] ----------------
__global__ void k_count(const int* __restrict__ edst) {
    int i = blockIdx.x * blockDim.x + threadIdx.x;
    if (i < NG * EG) { int g = i / EG; atomicAdd(&g_cnt[g * NPG + edst[i]], 1); }
}

__global__ void k_scan() {
    int g = blockIdx.x;
    __shared__ int ssum[1024];
    int t = threadIdx.x;
    const int per = (NPG + 1023) / 1024;
    int beg = t * per, end = min(beg + per, NPG);
    int s = 0;
    for (int i = beg; i < end; i++) s += g_cnt[g * NPG + i];
    ssum[t] = s;
    __syncthreads();
    for (int off = 1; off < 1024; off <<= 1) {
        int v = (t >= off) ? ssum[t - off] : 0;
        __syncthreads();
        ssum[t] += v;
        __syncthreads();
    }
    int run = (t == 0) ? 0 : ssum[t - 1];
    for (int i = beg; i < end; i++) { g_offs[g * (NPG + 1) + i] = run; run += g_cnt[g * NPG + i]; }
    if (t == 1023) g_offs[g * (NPG + 1) + NPG] = run;
}

__global__ void k_scatter(const int* __restrict__ esrc, const int* __restrict__ edst) {
    int i = blockIdx.x * blockDim.x + threadIdx.x;
    if (i < NG * EG) {
        int g = i / EG;
        int d = edst[i];
        int pos = g_offs[g * (NPG + 1) + d] + atomicAdd(&g_cur[g * NPG + d], 1);
        g_csr[g * EG + pos] = esrc[i];
    }
}

__global__ void k_flag(const int* __restrict__ tgt) {
    int i = blockIdx.x * blockDim.x + threadIdx.x;
    if (i < NG * TT) {
        int g = i / TT;
        int d = tgt[i];
        if (atomicExch(&g_flag[g * NPG + d], 1) == 0) {
            int p = atomicAdd(&g_wcnt[g], 1);
            g_list[g * TT + p] = d;
        }
    }
}

// ---------------- 4: single-pass edge softmax + aggregation  [R6 verbatim] ----------------
__global__ void k_agg() {
    int g = blockIdx.y;
    int widx = blockIdx.x * 8 + (threadIdx.x >> 5);
    if (widx >= g_wcnt[g]) return;
    int lane = threadIdx.x & 31;
    int half = lane >> 4;
    int sub  = lane & 15;
    int h    = sub >> 2;
    int dst  = g_list[g * TT + widx];
    int beg = g_offs[g * (NPG + 1) + dst];
    int end = g_offs[g * (NPG + 1) + dst + 1];
    const int*   csr = g_csr + g * EG;
    const float* elg = g_el + (size_t)g * NPG * NH;
    const float* zg  = g_z + (size_t)g * NPG * DD;
    float erh = g_er[(g * NPG + dst) * NH + h];
    float acc[16] = {};
    float denom = 0.f;
    for (int i = beg + half; i < end; i += 2) {
        int src = csr[i];
        float e  = lrelu(elg[src * NH + h] + erh);
        float ex = __expf(e);
        denom += ex;
        const float4* zp = (const float4*)(zg + (size_t)src * DD + sub * 16);
        float4 a = zp[0], b = zp[1], c = zp[2], d = zp[3];
        acc[0]  += ex * a.x; acc[1]  += ex * a.y; acc[2]  += ex * a.z; acc[3]  += ex * a.w;
        acc[4]  += ex * b.x; acc[5]  += ex * b.y; acc[6]  += ex * b.z; acc[7]  += ex * b.w;
        acc[8]  += ex * c.x; acc[9]  += ex * c.y; acc[10] += ex * c.z; acc[11] += ex * c.w;
        acc[12] += ex * d.x; acc[13] += ex * d.y; acc[14] += ex * d.z; acc[15] += ex * d.w;
    }
    denom += __shfl_xor_sync(~0u, denom, 16);
    #pragma unroll
    for (int j = 0; j < 16; j++) acc[j] += __shfl_xor_sync(~0u, acc[j], 16);
    if (half == 0) {
        float inv = 1.f / (denom + 1e-9f);
        float* op = g_o + ((size_t)g * NPG + dst) * DD + sub * 16;
        float4 v[4];
        #pragma unroll
        for (int j = 0; j < 16; j++) {
            float x = acc[j] * inv;
            ((float*)v)[j] = (x > 0.f) ? x : (__expf(x) - 1.f);
        }
        #pragma unroll
        for (int j = 0; j < 4; j++) ((float4*)op)[j] = v[j];
    }
}

// ---------------- 5: semantic score via bf16 tensor cores ----------------
// block: 256 thr = 8 warps; 32 rows/block (2 m-tiles of 16); each warp owns 32 cols
#define SEMX_STRIDE 132   // u32 stride per row (128 data + 4 pad) -> conflict-free A frags
__global__ void k_sem(const float* __restrict__ semb,
                      const float* __restrict__ semq, const int* __restrict__ tgt) {
    __shared__ uint32_t sxb[32 * SEMX_STRIDE];   // X tile in bf16x2
    __shared__ float sred[256];
    int g = blockIdx.y, b = g >> 1;
    int row0 = blockIdx.x * 32;
    int t = threadIdx.x;
    // gather + convert: 32 rows x 128 u32
    for (int i = t; i < 32 * 128; i += 256) {
        int r = i >> 7, c = i & 127;
        int node = tgt[g * TT + row0 + r];
        float2 xv = *(const float2*)(g_o + ((size_t)g * NPG + node) * DD + c * 2);
        sxb[r * SEMX_STRIDE + c] = bf2(xv.x, xv.y);
    }
    __syncthreads();
    int wid = t >> 5, lane = t & 31;
    int gid = lane >> 2, tid = lane & 3;
    int n0 = wid * 32;
    const uint32_t* Wb = (const uint32_t*)g_semWbt + (size_t)b * 32768;
    float c[2][4][4] = {};                      // [mtile][ntile][reg]
    for (int ks = 0; ks < 16; ks++) {
        int abase = ks * 8 + tid;
        uint32_t a[2][4];
        #pragma unroll
        for (int mt = 0; mt < 2; mt++) {
            int r = mt * 16 + gid;
            a[mt][0] = sxb[r * SEMX_STRIDE + abase];
            a[mt][1] = sxb[(r + 8) * SEMX_STRIDE + abase];
            a[mt][2] = sxb[r * SEMX_STRIDE + abase + 4];
            a[mt][3] = sxb[(r + 8) * SEMX_STRIDE + abase + 4];
        }
        #pragma unroll
        for (int nt = 0; nt < 4; nt++) {
            int n = n0 + nt * 8 + gid;
            uint32_t b0 = Wb[n * 128 + ks * 8 + tid];
            uint32_t b1 = Wb[n * 128 + ks * 8 + tid + 4];
            #pragma unroll
            for (int mt = 0; mt < 2; mt++)
                mma_bf16(c[mt][nt][0], c[mt][nt][1], c[mt][nt][2], c[mt][nt][3],
                         a[mt][0], a[mt][1], a[mt][2], a[mt][3], b0, b1);
        }
    }
    // epilogue: part += tanh(c + b[col]) * q[col]; rows irrelevant (summed anyway)
    float part = 0.f;
    #pragma unroll
    for (int nt = 0; nt < 4; nt++) {
        int col = n0 + nt * 8 + tid * 2;
        float2 bbv = *(const float2*)(semb + b * DD + col);
        float2 qqv = *(const float2*)(semq + b * DD + col);
        #pragma unroll
        for (int mt = 0; mt < 2; mt++) {
            part += tanh_fast(c[mt][nt][0] + bbv.x) * qqv.x;
            part += tanh_fast(c[mt][nt][1] + bbv.y) * qqv.y;
            part += tanh_fast(c[mt][nt][2] + bbv.x) * qqv.x;
            part += tanh_fast(c[mt][nt][3] + bbv.y) * qqv.y;
        }
    }
    sred[t] = part;
    __syncthreads();
    for (int s2 = 128; s2; s2 >>= 1) {
        if (t < s2) sred[t] += sred[t + s2];
        __syncthreads();
    }
    if (t == 0) atomicAdd(&g_wsum[g], sred[0]);
}

__global__ void k_beta() {
    if (threadIdx.x == 0 && blockIdx.x == 0) {
        for (int b = 0; b < 2; b++) {
            float w0 = g_wsum[b * 2 + 0] / (float)TT;
            float w1 = g_wsum[b * 2 + 1] / (float)TT;
            float mx = fmaxf(w0, w1);
            float e0 = __expf(w0 - mx), e1 = __expf(w1 - mx);
            float s = e0 + e1;
            g_beta[b * 2 + 0] = e0 / s;
            g_beta[b * 2 + 1] = e1 / s;
        }
    }
}

// ---------------- 6: beta-mix + fcout (32 rows/block, 256 thr)  [R6 verbatim] ----------------
#define OUT_PAD 34
__global__ void k_out(const float* __restrict__ foW, const float* __restrict__ fob,
                      const int* __restrict__ tgt, float* __restrict__ out) {
    int b = blockIdx.y;
    int row0 = blockIdx.x * 32;
    __shared__ float sx[256 * OUT_PAD];
    int t = threadIdx.x;
    float b0 = g_beta[b * 2], b1 = g_beta[b * 2 + 1];
    for (int i = t; i < 32 * 256; i += 256) {
        int r = i >> 8, k = i & 255;
        int row = row0 + r;
        int n0 = tgt[(b * 2 + 0) * TT + row];
        int n1 = tgt[(b * 2 + 1) * TT + row];
        sx[k * OUT_PAD + r] = b0 * g_o[((size_t)(b * 2 + 0) * NPG + n0) * DD + k]
                            + b1 * g_o[((size_t)(b * 2 + 1) * NPG + n1) * DD + k];
    }
    __syncthreads();
    int oq = t & 15, rg = t >> 4;
    const float* W = foW + (size_t)b * DD * OUTD;
    u64 acc0 = 0, acc1 = 0, acc2 = 0, acc3 = 0;
    #pragma unroll 4
    for (int k = 0; k < 256; k++) {
        float4 w = *(const float4*)(W + k * 64 + oq * 4);
        u64 xp = *(const u64*)&sx[k * OUT_PAD + rg * 2];
        u64 w0, w1, w2, w3;
        asm("mov.b64 %0, {%1, %1};" : "=l"(w0) : "f"(w.x));
        asm("mov.b64 %0, {%1, %1};" : "=l"(w1) : "f"(w.y));
        asm("mov.b64 %0, {%1, %1};" : "=l"(w2) : "f"(w.z));
        asm("mov.b64 %0, {%1, %1};" : "=l"(w3) : "f"(w.w));
        fma2(acc0, w0, xp); fma2(acc1, w1, xp);
        fma2(acc2, w2, xp); fma2(acc3, w3, xp);
    }
    float4 bb = *(const float4*)(fob + b * 64 + oq * 4);
    float2 a0 = unpack2(acc0), a1 = unpack2(acc1), a2 = unpack2(acc2), a3 = unpack2(acc3);
    int r0 = row0 + rg * 2;
    *(float4*)(out + ((size_t)b * TT + r0) * OUTD + oq * 4) =
        make_float4(a0.x + bb.x, a1.x + bb.y, a2.x + bb.z, a3.x + bb.w);
    *(float4*)(out + ((size_t)b * TT + r0 + 1) * OUTD + oq * 4) =
        make_float4(a0.y + bb.x, a1.y + bb.y, a2.y + bb.z, a3.y + bb.w);
}

// ---------------- launch ----------------
extern "C" void kernel_launch(void* const* d_in, const int* in_sizes, int n_in,
                              void* d_out, int out_size) {
    const float* features0 = (const float*)d_in[0];
    const float* features1 = (const float*)d_in[1];
    const float* fc_W      = (const float*)d_in[2];
    const float* fc_b      = (const float*)d_in[3];
    const float* gat_W     = (const float*)d_in[4];
    const float* attn_l    = (const float*)d_in[5];
    const float* attn_r    = (const float*)d_in[6];
    const float* sem_W     = (const float*)d_in[7];
    const float* sem_b     = (const float*)d_in[8];
    const float* sem_q     = (const float*)d_in[9];
    const float* fcout_W   = (const float*)d_in[10];
    const float* fcout_b   = (const float*)d_in[11];
    const int*   type_idx  = (const int*)d_in[12];
    const int*   node_idx  = (const int*)d_in[13];
    const int*   edge_src  = (const int*)d_in[14];
    const int*   edge_dst  = (const int*)d_in[15];
    const int*   tgt_idx   = (const int*)d_in[16];
    float* out = (float*)d_out;

    k_tw<<<640, 256>>>(fc_W, sem_W);                            // 1
    k_zero<<<(NG * NPG + 255) / 256, 256>>>();                  // 2
    {
        dim3 grid(NPT / 16, 2);
        k_fc<<<grid, 128>>>(features0, features1, fc_b, type_idx);  // 3
    }
    {
        dim3 grid(NPG / 16, NG);
        k_gatz<<<grid, 256>>>(gat_W, node_idx, attn_l, attn_r); // 4 <- ncu capture slot
    }
    k_count<<<(NG * EG + 255) / 256, 256>>>(edge_dst);
    k_scan<<<NG, 1024>>>();
    k_scatter<<<(NG * EG + 255) / 256, 256>>>(edge_src, edge_dst);
    k_flag<<<(NG * TT + 255) / 256, 256>>>(tgt_idx);
    {
        dim3 grid((TT + 7) / 8, NG);
        k_agg<<<grid, 256>>>();
    }
    {
        dim3 grid(TT / 32, NG);
        k_sem<<<grid, 256>>>(sem_b, sem_q, tgt_idx);
    }
    k_beta<<<1, 32>>>();
    {
        dim3 grid(TT / 32, 2);
        k_out<<<grid, 256>>>(fcout_b ? fcout_W : fcout_W, fcout_b, tgt_idx, out);
    }
}

// round 13
// speedup vs baseline: 2.2365x; 1.0901x over previous
#include <cuda_runtime.h>
#include <cuda_bf16.h>
#include <cstdint>
#include <cstddef>

// ---------------- problem constants ----------------
#define NTOT   100000
#define NPT    50000
#define NPG    50000
#define EG     500000
#define NG     4
#define NH     4
#define HD     64
#define HID    64
#define DD     256
#define OUTD   64
#define TT     20000

typedef unsigned long long u64;

// ---------------- device scratch (static, no allocs) ----------------
__device__ float g_transformed[(size_t)NTOT * HID];
__device__ float g_fcWt[2 * 256 * 64];                 // fc_W transposed [ty][k][o]
__device__ __nv_bfloat16 g_semWbt[2 * 256 * 256];      // sem_W bf16 transposed [b][n][k]
__device__ uint32_t g_gatWhi[4 * 256 * 32];            // gat_W bf16 hi [g][n][kpair]
__device__ uint32_t g_gatWlo[4 * 256 * 32];            // gat_W bf16 lo residual
__device__ float g_z[(size_t)NG * NPG * DD];
__device__ float g_el[NG * NPG * NH];
__device__ float g_er[NG * NPG * NH];
__device__ int   g_cnt[NG * NPG];
__device__ int   g_cur[NG * NPG];
__device__ int   g_offs[NG * (NPG + 1)];
__device__ int   g_csr[NG * EG];
__device__ int   g_flag[NG * NPG];
__device__ int   g_list[NG * TT];
__device__ int   g_wcnt[NG];
__device__ float g_o[(size_t)NG * NPG * DD];
__device__ float g_wsum[NG];
__device__ float g_beta[NG];

__device__ __forceinline__ float lrelu(float x) { return fmaxf(x, 0.2f * x); }
__device__ __forceinline__ float tanh_fast(float x) {
    float y; asm("tanh.approx.f32 %0, %1;" : "=f"(y) : "f"(x)); return y;
}
__device__ __forceinline__ void fma2(u64& acc, u64 a, u64 b) {
    asm("fma.rn.f32x2 %0, %1, %2, %0;" : "+l"(acc) : "l"(a), "l"(b));
}
__device__ __forceinline__ float2 unpack2(u64 v) {
    float2 r; asm("mov.b64 {%0, %1}, %2;" : "=f"(r.x), "=f"(r.y) : "l"(v)); return r;
}
__device__ __forceinline__ u64 add2(u64 a, u64 b) {
    u64 d; asm("add.rn.f32x2 %0, %1, %2;" : "=l"(d) : "l"(a), "l"(b)); return d;
}
// pack (lo,hi) floats into bf16x2 (lo = element 0)
__device__ __forceinline__ uint32_t bf2(float lo, float hi) {
    uint32_t r; asm("cvt.rn.bf16x2.f32 %0, %1, %2;" : "=r"(r) : "f"(hi), "f"(lo)); return r;
}
__device__ __forceinline__ void mma_bf16(float& c0, float& c1, float& c2, float& c3,
                                         uint32_t a0, uint32_t a1, uint32_t a2, uint32_t a3,
                                         uint32_t b0, uint32_t b1) {
    asm("mma.sync.aligned.m16n8k16.row.col.f32.bf16.bf16.f32 "
        "{%0,%1,%2,%3},{%4,%5,%6,%7},{%8,%9},{%0,%1,%2,%3};"
        : "+f"(c0), "+f"(c1), "+f"(c2), "+f"(c3)
        : "r"(a0), "r"(a1), "r"(a2), "r"(a3), "r"(b0), "r"(b1));
}

// ---------------- weight prep ----------------
__global__ void k_tw(const float* __restrict__ fcW, const float* __restrict__ semW,
                     const float* __restrict__ gatW) {
    int i = blockIdx.x * blockDim.x + threadIdx.x;
    if (i < 2 * 256 * 64) {                    // fcWt [ty][k][o]
        int ty = i >> 14, rem = i & 16383, k = rem >> 6, o = rem & 63;
        g_fcWt[i] = fcW[ty * 16384 + o * 256 + k];
    }
    int j = i - 2 * 256 * 64;
    if (j >= 0 && j < 2 * 256 * 256) {         // semWbt [b][n][k] <- semW [b][k][n]
        int b = j >> 16, rem = j & 65535, n = rem >> 8, k = rem & 255;
        g_semWbt[j] = __float2bfloat16(semW[b * 65536 + k * 256 + n]);
    }
    int j2 = i - 2 * 256 * 64 - 2 * 256 * 256;
    if (j2 >= 0 && j2 < 4 * 256 * 32) {        // gat hi/lo [g][n][kpair]
        int g = j2 >> 13, rem = j2 & 8191, n = rem >> 5, kp = rem & 31;
        const float* Wg = gatW + (size_t)g * 64 * 256;
        float w0 = Wg[(2 * kp) * 256 + n];
        float w1 = Wg[(2 * kp + 1) * 256 + n];
        uint32_t hp = bf2(w0, w1);
        g_gatWhi[j2] = hp;
        float h0 = __uint_as_float(hp << 16);
        float h1 = __uint_as_float(hp & 0xffff0000u);
        g_gatWlo[j2] = bf2(w0 - h0, w1 - h1);
    }
}

// ---------------- zero per-call scratch ----------------
__global__ void k_zero() {
    int i = blockIdx.x * blockDim.x + threadIdx.x;
    if (i < NG * NPG) { g_cnt[i] = 0; g_cur[i] = 0; g_flag[i] = 0; }
    if (i < NG) { g_wsum[i] = 0.f; g_wcnt[i] = 0; }
}

// ---------------- 1: type FC (16 rows/block, 128 thr) ----------------
__global__ void k_fc(const float* __restrict__ f0, const float* __restrict__ f1,
                     const float* __restrict__ fcb, const int* __restrict__ type_idx) {
    int ty = blockIdx.y;
    int row0 = blockIdx.x * 16;
    __shared__ float sx[256 * 18];
    int t = threadIdx.x;                      // 128
    const float* f = (ty == 0 ? f0 : f1);
    for (int i = t; i < 16 * 256; i += 128) {
        int r = i >> 8, k = i & 255;
        sx[k * 18 + r] = f[(size_t)(row0 + r) * 256 + k];
    }
    __syncthreads();
    int oq = t & 15, rg = t >> 4;
    const float* Wt = g_fcWt + ty * 16384;
    u64 acc0 = 0, acc1 = 0, acc2 = 0, acc3 = 0;
    #pragma unroll 4
    for (int k = 0; k < 256; k++) {
        float4 w = *(const float4*)(Wt + k * 64 + oq * 4);
        u64 xp = *(const u64*)&sx[k * 18 + rg * 2];
        u64 w0, w1, w2, w3;
        asm("mov.b64 %0, {%1, %1};" : "=l"(w0) : "f"(w.x));
        asm("mov.b64 %0, {%1, %1};" : "=l"(w1) : "f"(w.y));
        asm("mov.b64 %0, {%1, %1};" : "=l"(w2) : "f"(w.z));
        asm("mov.b64 %0, {%1, %1};" : "=l"(w3) : "f"(w.w));
        fma2(acc0, w0, xp); fma2(acc1, w1, xp);
        fma2(acc2, w2, xp); fma2(acc3, w3, xp);
    }
    float4 bb = *(const float4*)(fcb + ty * 64 + oq * 4);
    float2 a0 = unpack2(acc0), a1 = unpack2(acc1), a2 = unpack2(acc2), a3 = unpack2(acc3);
    int r0 = row0 + rg * 2;
    int d0 = type_idx[ty * NPT + r0];
    int d1 = type_idx[ty * NPT + r0 + 1];
    *(float4*)(g_transformed + (size_t)d0 * 64 + oq * 4) =
        make_float4(a0.x + bb.x, a1.x + bb.y, a2.x + bb.z, a3.x + bb.w);
    *(float4*)(g_transformed + (size_t)d1 * 64 + oq * 4) =
        make_float4(a0.y + bb.x, a1.y + bb.y, a2.y + bb.z, a3.y + bb.w);
}

// ---------------- 2: gather + z = h @ gat_W via split-bf16 MMA, fused el/er ----------------
// 32 rows/block (2 m-tiles), 256 thr = 8 warps; warp w owns cols w*32..w*32+31
#define GA_S 36
__global__ void k_gatz(const int* __restrict__ node_idx,
                       const float* __restrict__ al, const float* __restrict__ ar) {
    __shared__ uint32_t ahi[32 * GA_S], alo[32 * GA_S];
    __shared__ float sel[32][NH], ser[32][NH];
    int g = blockIdx.y;
    int row0 = blockIdx.x * 32;
    int t = threadIdx.x;
    if (t < 128) { sel[t >> 2][t & 3] = 0.f; ser[t >> 2][t & 3] = 0.f; }
    // gather + hi/lo split convert: 32 rows x 32 u32 (64 bf16)
    for (int i = t; i < 32 * 32; i += 256) {
        int r = i >> 5, c = i & 31;
        int rr = row0 + r; rr = rr < NPG ? rr : NPG - 1;
        int node = node_idx[g * NPG + rr];
        float2 xv = *(const float2*)(g_transformed + (size_t)node * 64 + c * 2);
        uint32_t hp = bf2(xv.x, xv.y);
        float h0 = __uint_as_float(hp << 16);
        float h1 = __uint_as_float(hp & 0xffff0000u);
        ahi[r * GA_S + c] = hp;
        alo[r * GA_S + c] = bf2(xv.x - h0, xv.y - h1);
    }
    __syncthreads();
    int wid = t >> 5, lane = t & 31;
    int gid = lane >> 2, tid = lane & 3;
    int n0 = wid * 32;
    const uint32_t* Whi = g_gatWhi + (size_t)g * 8192;   // [n=256][kp=32]
    const uint32_t* Wlo = g_gatWlo + (size_t)g * 8192;
    float c[2][4][4] = {};
    #pragma unroll
    for (int ks = 0; ks < 4; ks++) {
        int ab = ks * 8 + tid;
        uint32_t ah[2][4], av[2][4];
        #pragma unroll
        for (int mt = 0; mt < 2; mt++) {
            int r = mt * 16 + gid;
            ah[mt][0] = ahi[r * GA_S + ab];           av[mt][0] = alo[r * GA_S + ab];
            ah[mt][1] = ahi[(r + 8) * GA_S + ab];     av[mt][1] = alo[(r + 8) * GA_S + ab];
            ah[mt][2] = ahi[r * GA_S + ab + 4];       av[mt][2] = alo[r * GA_S + ab + 4];
            ah[mt][3] = ahi[(r + 8) * GA_S + ab + 4]; av[mt][3] = alo[(r + 8) * GA_S + ab + 4];
        }
        #pragma unroll
        for (int nt = 0; nt < 4; nt++) {
            int n = n0 + nt * 8 + gid;
            uint32_t bh0 = Whi[n * 32 + ks * 8 + tid];
            uint32_t bh1 = Whi[n * 32 + ks * 8 + tid + 4];
            uint32_t bl0 = Wlo[n * 32 + ks * 8 + tid];
            uint32_t bl1 = Wlo[n * 32 + ks * 8 + tid + 4];
            #pragma unroll
            for (int mt = 0; mt < 2; mt++) {
                mma_bf16(c[mt][nt][0], c[mt][nt][1], c[mt][nt][2], c[mt][nt][3],
                         ah[mt][0], ah[mt][1], ah[mt][2], ah[mt][3], bh0, bh1);
                mma_bf16(c[mt][nt][0], c[mt][nt][1], c[mt][nt][2], c[mt][nt][3],
                         ah[mt][0], ah[mt][1], ah[mt][2], ah[mt][3], bl0, bl1);
                mma_bf16(c[mt][nt][0], c[mt][nt][1], c[mt][nt][2], c[mt][nt][3],
                         av[mt][0], av[mt][1], av[mt][2], av[mt][3], bh0, bh1);
            }
        }
    }
    // epilogue: store z + per-row el/er partials over this warp's 32 cols
    float pl[2][2] = {}, pr[2][2] = {};
    #pragma unroll
    for (int mt = 0; mt < 2; mt++) {
        #pragma unroll
        for (int nt = 0; nt < 4; nt++) {
            int col = n0 + nt * 8 + tid * 2;
            float2 av2 = *(const float2*)(al + g * DD + col);
            float2 rv2 = *(const float2*)(ar + g * DD + col);
            pl[mt][0] += c[mt][nt][0] * av2.x + c[mt][nt][1] * av2.y;
            pl[mt][1] += c[mt][nt][2] * av2.x + c[mt][nt][3] * av2.y;
            pr[mt][0] += c[mt][nt][0] * rv2.x + c[mt][nt][1] * rv2.y;
            pr[mt][1] += c[mt][nt][2] * rv2.x + c[mt][nt][3] * rv2.y;
            int r0 = row0 + mt * 16 + gid;
            if (r0 < NPG)
                *(float2*)(g_z + ((size_t)g * NPG + r0) * DD + col) =
                    make_float2(c[mt][nt][0], c[mt][nt][1]);
            if (r0 + 8 < NPG)
                *(float2*)(g_z + ((size_t)g * NPG + r0 + 8) * DD + col) =
                    make_float2(c[mt][nt][2], c[mt][nt][3]);
        }
    }
    #pragma unroll
    for (int off = 1; off < 4; off <<= 1) {
        #pragma unroll
        for (int mt = 0; mt < 2; mt++) {
            #pragma unroll
            for (int rp = 0; rp < 2; rp++) {
                pl[mt][rp] += __shfl_xor_sync(~0u, pl[mt][rp], off);
                pr[mt][rp] += __shfl_xor_sync(~0u, pr[mt][rp], off);
            }
        }
    }
    if (tid == 0) {
        int h = wid >> 1;                     // two warps per head
        #pragma unroll
        for (int mt = 0; mt < 2; mt++) {
            #pragma unroll
            for (int rp = 0; rp < 2; rp++) {
                int r = mt * 16 + gid + rp * 8;
                atomicAdd(&sel[r][h], pl[mt][rp]);
                atomicAdd(&ser[r][h], pr[mt][rp]);
            }
        }
    }
    __syncthreads();
    if (t < 128) {
        int r = t >> 2, h = t & 3;
        int row = row0 + r;
        if (row < NPG) {
            g_el[((size_t)g * NPG + row) * NH + h] = sel[r][h];
            g_er[((size_t)g * NPG + row) * NH + h] = ser[r][h];
        }
    }
}

// ---------------- 3: CSR build ----------------
__global__ void k_count(const int* __restrict__ edst) {
    int i = blockIdx.x * blockDim.x + threadIdx.x;
    if (i < NG * EG) { int g = i / EG; atomicAdd(&g_cnt[g * NPG + edst[i]], 1); }
}

__global__ void k_scan() {
    int g = blockIdx.x;
    __shared__ int ssum[1024];
    int t = threadIdx.x;
    const int per = (NPG + 1023) / 1024;
    int beg = t * per, end = min(beg + per, NPG);
    int s = 0;
    for (int i = beg; i < end; i++) s += g_cnt[g * NPG + i];
    ssum[t] = s;
    __syncthreads();
    for (int off = 1; off < 1024; off <<= 1) {
        int v = (t >= off) ? ssum[t - off] : 0;
        __syncthreads();
        ssum[t] += v;
        __syncthreads();
    }
    int run = (t == 0) ? 0 : ssum[t - 1];
    for (int i = beg; i < end; i++) { g_offs[g * (NPG + 1) + i] = run; run += g_cnt[g * NPG + i]; }
    if (t == 1023) g_offs[g * (NPG + 1) + NPG] = run;
}

__global__ void k_scatter(const int* __restrict__ esrc, const int* __restrict__ edst) {
    int i = blockIdx.x * blockDim.x + threadIdx.x;
    if (i < NG * EG) {
        int g = i / EG;
        int d = edst[i];
        int pos = g_offs[g * (NPG + 1) + d] + atomicAdd(&g_cur[g * NPG + d], 1);
        g_csr[g * EG + pos] = esrc[i];
    }
}

__global__ void k_flag(const int* __restrict__ tgt) {
    int i = blockIdx.x * blockDim.x + threadIdx.x;
    if (i < NG * TT) {
        int g = i / TT;
        int d = tgt[i];
        if (atomicExch(&g_flag[g * NPG + d], 1) == 0) {
            int p = atomicAdd(&g_wcnt[g], 1);
            g_list[g * TT + p] = d;
        }
    }
}

// ---------------- 4: single-pass edge softmax + aggregation ----------------
__global__ void k_agg() {
    int g = blockIdx.y;
    int widx = blockIdx.x * 8 + (threadIdx.x >> 5);
    if (widx >= g_wcnt[g]) return;
    int lane = threadIdx.x & 31;
    int half = lane >> 4;
    int sub  = lane & 15;
    int h    = sub >> 2;
    int dst  = g_list[g * TT + widx];
    int beg = g_offs[g * (NPG + 1) + dst];
    int end = g_offs[g * (NPG + 1) + dst + 1];
    const int*   csr = g_csr + g * EG;
    const float* elg = g_el + (size_t)g * NPG * NH;
    const float* zg  = g_z + (size_t)g * NPG * DD;
    float erh = g_er[(g * NPG + dst) * NH + h];
    float acc[16] = {};
    float denom = 0.f;
    for (int i = beg + half; i < end; i += 2) {
        int src = csr[i];
        float e  = lrelu(elg[src * NH + h] + erh);
        float ex = __expf(e);
        denom += ex;
        const float4* zp = (const float4*)(zg + (size_t)src * DD + sub * 16);
        float4 a = zp[0], b = zp[1], c = zp[2], d = zp[3];
        acc[0]  += ex * a.x; acc[1]  += ex * a.y; acc[2]  += ex * a.z; acc[3]  += ex * a.w;
        acc[4]  += ex * b.x; acc[5]  += ex * b.y; acc[6]  += ex * b.z; acc[7]  += ex * b.w;
        acc[8]  += ex * c.x; acc[9]  += ex * c.y; acc[10] += ex * c.z; acc[11] += ex * c.w;
        acc[12] += ex * d.x; acc[13] += ex * d.y; acc[14] += ex * d.z; acc[15] += ex * d.w;
    }
    denom += __shfl_xor_sync(~0u, denom, 16);
    #pragma unroll
    for (int j = 0; j < 16; j++) acc[j] += __shfl_xor_sync(~0u, acc[j], 16);
    if (half == 0) {
        float inv = 1.f / (denom + 1e-9f);
        float* op = g_o + ((size_t)g * NPG + dst) * DD + sub * 16;
        float4 v[4];
        #pragma unroll
        for (int j = 0; j < 16; j++) {
            float x = acc[j] * inv;
            ((float*)v)[j] = (x > 0.f) ? x : (__expf(x) - 1.f);
        }
        #pragma unroll
        for (int j = 0; j < 4; j++) ((float4*)op)[j] = v[j];
    }
}

// ---------------- 5: semantic score via bf16 tensor cores ----------------
#define SEMX_STRIDE 132
__global__ void k_sem(const float* __restrict__ semb,
                      const float* __restrict__ semq, const int* __restrict__ tgt) {
    __shared__ uint32_t sxb[32 * SEMX_STRIDE];
    __shared__ float sred[256];
    int g = blockIdx.y, b = g >> 1;
    int row0 = blockIdx.x * 32;
    int t = threadIdx.x;
    for (int i = t; i < 32 * 128; i += 256) {
        int r = i >> 7, c = i & 127;
        int node = tgt[g * TT + row0 + r];
        float2 xv = *(const float2*)(g_o + ((size_t)g * NPG + node) * DD + c * 2);
        sxb[r * SEMX_STRIDE + c] = bf2(xv.x, xv.y);
    }
    __syncthreads();
    int wid = t >> 5, lane = t & 31;
    int gid = lane >> 2, tid = lane & 3;
    int n0 = wid * 32;
    const uint32_t* Wb = (const uint32_t*)g_semWbt + (size_t)b * 32768;
    float c[2][4][4] = {};
    for (int ks = 0; ks < 16; ks++) {
        int abase = ks * 8 + tid;
        uint32_t a[2][4];
        #pragma unroll
        for (int mt = 0; mt < 2; mt++) {
            int r = mt * 16 + gid;
            a[mt][0] = sxb[r * SEMX_STRIDE + abase];
            a[mt][1] = sxb[(r + 8) * SEMX_STRIDE + abase];
            a[mt][2] = sxb[r * SEMX_STRIDE + abase + 4];
            a[mt][3] = sxb[(r + 8) * SEMX_STRIDE + abase + 4];
        }
        #pragma unroll
        for (int nt = 0; nt < 4; nt++) {
            int n = n0 + nt * 8 + gid;
            uint32_t b0 = Wb[n * 128 + ks * 8 + tid];
            uint32_t b1 = Wb[n * 128 + ks * 8 + tid + 4];
            #pragma unroll
            for (int mt = 0; mt < 2; mt++)
                mma_bf16(c[mt][nt][0], c[mt][nt][1], c[mt][nt][2], c[mt][nt][3],
                         a[mt][0], a[mt][1], a[mt][2], a[mt][3], b0, b1);
        }
    }
    float part = 0.f;
    #pragma unroll
    for (int nt = 0; nt < 4; nt++) {
        int col = n0 + nt * 8 + tid * 2;
        float2 bbv = *(const float2*)(semb + b * DD + col);
        float2 qqv = *(const float2*)(semq + b * DD + col);
        #pragma unroll
        for (int mt = 0; mt < 2; mt++) {
            part += tanh_fast(c[mt][nt][0] + bbv.x) * qqv.x;
            part += tanh_fast(c[mt][nt][1] + bbv.y) * qqv.y;
            part += tanh_fast(c[mt][nt][2] + bbv.x) * qqv.x;
            part += tanh_fast(c[mt][nt][3] + bbv.y) * qqv.y;
        }
    }
    sred[t] = part;
    __syncthreads();
    for (int s2 = 128; s2; s2 >>= 1) {
        if (t < s2) sred[t] += sred[t + s2];
        __syncthreads();
    }
    if (t == 0) atomicAdd(&g_wsum[g], sred[0]);
}

__global__ void k_beta() {
    if (threadIdx.x == 0 && blockIdx.x == 0) {
        for (int b = 0; b < 2; b++) {
            float w0 = g_wsum[b * 2 + 0] / (float)TT;
            float w1 = g_wsum[b * 2 + 1] / (float)TT;
            float mx = fmaxf(w0, w1);
            float e0 = __expf(w0 - mx), e1 = __expf(w1 - mx);
            float s = e0 + e1;
            g_beta[b * 2 + 0] = e0 / s;
            g_beta[b * 2 + 1] = e1 / s;
        }
    }
}

// ---------------- 6: beta-mix + fcout (32 rows/block, 256 thr) ----------------
#define OUT_PAD 34
__global__ void k_out(const float* __restrict__ foW, const float* __restrict__ fob,
                      const int* __restrict__ tgt, float* __restrict__ out) {
    int b = blockIdx.y;
    int row0 = blockIdx.x * 32;
    __shared__ float sx[256 * OUT_PAD];
    int t = threadIdx.x;
    float b0 = g_beta[b * 2], b1 = g_beta[b * 2 + 1];
    for (int i = t; i < 32 * 256; i += 256) {
        int r = i >> 8, k = i & 255;
        int row = row0 + r;
        int n0 = tgt[(b * 2 + 0) * TT + row];
        int n1 = tgt[(b * 2 + 1) * TT + row];
        sx[k * OUT_PAD + r] = b0 * g_o[((size_t)(b * 2 + 0) * NPG + n0) * DD + k]
                            + b1 * g_o[((size_t)(b * 2 + 1) * NPG + n1) * DD + k];
    }
    __syncthreads();
    int oq = t & 15, rg = t >> 4;
    const float* W = foW + (size_t)b * DD * OUTD;
    u64 acc0 = 0, acc1 = 0, acc2 = 0, acc3 = 0;
    #pragma unroll 4
    for (int k = 0; k < 256; k++) {
        float4 w = *(const float4*)(W + k * 64 + oq * 4);
        u64 xp = *(const u64*)&sx[k * OUT_PAD + rg * 2];
        u64 w0, w1, w2, w3;
        asm("mov.b64 %0, {%1, %1};" : "=l"(w0) : "f"(w.x));
        asm("mov.b64 %0, {%1, %1};" : "=l"(w1) : "f"(w.y));
        asm("mov.b64 %0, {%1, %1};" : "=l"(w2) : "f"(w.z));
        asm("mov.b64 %0, {%1, %1};" : "=l"(w3) : "f"(w.w));
        fma2(acc0, w0, xp); fma2(acc1, w1, xp);
        fma2(acc2, w2, xp); fma2(acc3, w3, xp);
    }
    float4 bb = *(const float4*)(fob + b * 64 + oq * 4);
    float2 a0 = unpack2(acc0), a1 = unpack2(acc1), a2 = unpack2(acc2), a3 = unpack2(acc3);
    int r0 = row0 + rg * 2;
    *(float4*)(out + ((size_t)b * TT + r0) * OUTD + oq * 4) =
        make_float4(a0.x + bb.x, a1.x + bb.y, a2.x + bb.z, a3.x + bb.w);
    *(float4*)(out + ((size_t)b * TT + r0 + 1) * OUTD + oq * 4) =
        make_float4(a0.y + bb.x, a1.y + bb.y, a2.y + bb.z, a3.y + bb.w);
}

// ---------------- launch ----------------
extern "C" void kernel_launch(void* const* d_in, const int* in_sizes, int n_in,
                              void* d_out, int out_size) {
    const float* features0 = (const float*)d_in[0];
    const float* features1 = (const float*)d_in[1];
    const float* fc_W      = (const float*)d_in[2];
    const float* fc_b      = (const float*)d_in[3];
    const float* gat_W     = (const float*)d_in[4];
    const float* attn_l    = (const float*)d_in[5];
    const float* attn_r    = (const float*)d_in[6];
    const float* sem_W     = (const float*)d_in[7];
    const float* sem_b     = (const float*)d_in[8];
    const float* sem_q     = (const float*)d_in[9];
    const float* fcout_W   = (const float*)d_in[10];
    const float* fcout_b   = (const float*)d_in[11];
    const int*   type_idx  = (const int*)d_in[12];
    const int*   node_idx  = (const int*)d_in[13];
    const int*   edge_src  = (const int*)d_in[14];
    const int*   edge_dst  = (const int*)d_in[15];
    const int*   tgt_idx   = (const int*)d_in[16];
    float* out = (float*)d_out;

    k_tw<<<768, 256>>>(fc_W, sem_W, gat_W);                     // 1
    k_zero<<<(NG * NPG + 255) / 256, 256>>>();                  // 2
    {
        dim3 grid(NPT / 16, 2);
        k_fc<<<grid, 128>>>(features0, features1, fc_b, type_idx);  // 3
    }
    {
        dim3 grid((NPG + 31) / 32, NG);
        k_gatz<<<grid, 256>>>(node_idx, attn_l, attn_r);        // 4 <- ncu capture slot
    }
    k_count<<<(NG * EG + 255) / 256, 256>>>(edge_dst);
    k_scan<<<NG, 1024>>>();
    k_scatter<<<(NG * EG + 255) / 256, 256>>>(edge_src, edge_dst);
    k_flag<<<(NG * TT + 255) / 256, 256>>>(tgt_idx);
    {
        dim3 grid((TT + 7) / 8, NG);
        k_agg<<<grid, 256>>>();
    }
    {
        dim3 grid(TT / 32, NG);
        k_sem<<<grid, 256>>>(sem_b, sem_q, tgt_idx);
    }
    k_beta<<<1, 32>>>();
    {
        dim3 grid(TT / 32, 2);
        k_out<<<grid, 256>>>(fcout_W, fcout_b, tgt_idx, out);
    }
}

// round 15
// speedup vs baseline: 2.3517x; 1.0515x over previous
#include <cuda_runtime.h>
#include <cuda_bf16.h>
#include <cstdint>
#include <cstddef>

// ---------------- problem constants ----------------
#define NTOT   100000
#define NPT    50000
#define NPG    50000
#define EG     500000
#define NG     4
#define NH     4
#define HD     64
#define HID    64
#define DD     256
#define OUTD   64
#define TT     20000

typedef unsigned long long u64;

// ---------------- device scratch (static, no allocs) ----------------
__device__ float g_transformed[(size_t)NTOT * HID];
__device__ __nv_bfloat16 g_semWbt[2 * 256 * 256];      // sem_W bf16 transposed [b][n][k]
__device__ uint32_t g_gatWhi[4 * 256 * 32];            // gat_W bf16 hi [g][n][kpair]
__device__ uint32_t g_gatWlo[4 * 256 * 32];            // gat_W bf16 lo residual
__device__ uint32_t g_fcWhi[2 * 64 * 128];             // fc_W bf16 hi [ty][n][kpair]
__device__ uint32_t g_fcWlo[2 * 64 * 128];             // fc_W bf16 lo residual
__device__ float g_z[(size_t)NG * NPG * DD];
__device__ float g_el[NG * NPG * NH];
__device__ float g_er[NG * NPG * NH];
__device__ int   g_cnt[NG * NPG];
__device__ int   g_cur[NG * NPG];
__device__ int   g_offs[NG * (NPG + 1)];
__device__ int   g_csr[NG * EG];
__device__ int   g_flag[NG * NPG];
__device__ int   g_list[NG * TT];
__device__ int   g_wcnt[NG];
__device__ float g_o[(size_t)NG * NPG * DD];
__device__ float g_wsum[NG];
__device__ float g_beta[NG];

__device__ __forceinline__ float lrelu(float x) { return fmaxf(x, 0.2f * x); }
__device__ __forceinline__ float tanh_fast(float x) {
    float y; asm("tanh.approx.f32 %0, %1;" : "=f"(y) : "f"(x)); return y;
}
__device__ __forceinline__ void fma2(u64& acc, u64 a, u64 b) {
    asm("fma.rn.f32x2 %0, %1, %2, %0;" : "+l"(acc) : "l"(a), "l"(b));
}
__device__ __forceinline__ float2 unpack2(u64 v) {
    float2 r; asm("mov.b64 {%0, %1}, %2;" : "=f"(r.x), "=f"(r.y) : "l"(v)); return r;
}
// pack (lo,hi) floats into bf16x2 (lo = element 0)
__device__ __forceinline__ uint32_t bf2(float lo, float hi) {
    uint32_t r; asm("cvt.rn.bf16x2.f32 %0, %1, %2;" : "=r"(r) : "f"(hi), "f"(lo)); return r;
}
__device__ __forceinline__ void mma_bf16(float& c0, float& c1, float& c2, float& c3,
                                         uint32_t a0, uint32_t a1, uint32_t a2, uint32_t a3,
                                         uint32_t b0, uint32_t b1) {
    asm("mma.sync.aligned.m16n8k16.row.col.f32.bf16.bf16.f32 "
        "{%0,%1,%2,%3},{%4,%5,%6,%7},{%8,%9},{%0,%1,%2,%3};"
        : "+f"(c0), "+f"(c1), "+f"(c2), "+f"(c3)
        : "r"(a0), "r"(a1), "r"(a2), "r"(a3), "r"(b0), "r"(b1));
}

// ---------------- weight prep ----------------
__global__ void k_tw(const float* __restrict__ fcW, const float* __restrict__ semW,
                     const float* __restrict__ gatW) {
    int i = blockIdx.x * blockDim.x + threadIdx.x;
    if (i < 2 * 256 * 256) {                   // semWbt [b][n][k] <- semW [b][k][n]
        int b = i >> 16, rem = i & 65535, n = rem >> 8, k = rem & 255;
        g_semWbt[i] = __float2bfloat16(semW[b * 65536 + k * 256 + n]);
    }
    int j2 = i - 2 * 256 * 256;
    if (j2 >= 0 && j2 < 4 * 256 * 32) {        // gat hi/lo [g][n][kpair]
        int g = j2 >> 13, rem = j2 & 8191, n = rem >> 5, kp = rem & 31;
        const float* Wg = gatW + (size_t)g * 64 * 256;
        float w0 = Wg[(2 * kp) * 256 + n];
        float w1 = Wg[(2 * kp + 1) * 256 + n];
        uint32_t hp = bf2(w0, w1);
        g_gatWhi[j2] = hp;
        float h0 = __uint_as_float(hp << 16);
        float h1 = __uint_as_float(hp & 0xffff0000u);
        g_gatWlo[j2] = bf2(w0 - h0, w1 - h1);
    }
    int j3 = i - 2 * 256 * 256 - 4 * 256 * 32;
    if (j3 >= 0 && j3 < 2 * 64 * 128) {        // fc hi/lo [ty][n][kpair], fcW is [ty][o][k]
        int ty = j3 >> 13, rem = j3 & 8191, n = rem >> 7, kp = rem & 127;
        const float* Wt = fcW + ty * 16384 + n * 256;
        float w0 = Wt[2 * kp];
        float w1 = Wt[2 * kp + 1];
        uint32_t hp = bf2(w0, w1);
        g_fcWhi[j3] = hp;
        float h0 = __uint_as_float(hp << 16);
        float h1 = __uint_as_float(hp & 0xffff0000u);
        g_fcWlo[j3] = bf2(w0 - h0, w1 - h1);
    }
}

// ---------------- zero per-call scratch ----------------
__global__ void k_zero() {
    int i = blockIdx.x * blockDim.x + threadIdx.x;
    if (i < NG * NPG) { g_cnt[i] = 0; g_cur[i] = 0; g_flag[i] = 0; }
    if (i < NG) { g_wsum[i] = 0.f; g_wcnt[i] = 0; }
}

// ---------------- 1: type FC via split-bf16 MMA ----------------
// 32 rows/block, 256 thr = 8 warps: mt = wid>>2 (2 m-tiles), cq = wid&3 (16 cols each)
#define FC_S 132
__global__ void k_fc(const float* __restrict__ f0, const float* __restrict__ f1,
                     const float* __restrict__ fcb, const int* __restrict__ type_idx) {
    __shared__ uint32_t ahi[32 * FC_S], alo[32 * FC_S];
    int ty = blockIdx.y;
    int row0 = blockIdx.x * 32;
    int t = threadIdx.x;
    const float* f = (ty == 0 ? f0 : f1);
    for (int i = t; i < 32 * 128; i += 256) {
        int r = i >> 7, c = i & 127;
        int rr = row0 + r; rr = rr < NPT ? rr : NPT - 1;
        float2 xv = *(const float2*)(f + (size_t)rr * 256 + c * 2);
        uint32_t hp = bf2(xv.x, xv.y);
        float h0 = __uint_as_float(hp << 16);
        float h1 = __uint_as_float(hp & 0xffff0000u);
        ahi[r * FC_S + c] = hp;
        alo[r * FC_S + c] = bf2(xv.x - h0, xv.y - h1);
    }
    __syncthreads();
    int wid = t >> 5, lane = t & 31;
    int gid = lane >> 2, tid = lane & 3;
    int mt = wid >> 2, cq = wid & 3;
    const uint32_t* Whi = g_fcWhi + ty * 8192;   // [n=64][kp=128]
    const uint32_t* Wlo = g_fcWlo + ty * 8192;
    float c[2][4] = {};                          // [ntile][reg]
    #pragma unroll
    for (int ks = 0; ks < 16; ks++) {
        int ab = ks * 8 + tid;
        int r = mt * 16 + gid;
        uint32_t a0 = ahi[r * FC_S + ab];
        uint32_t a1 = ahi[(r + 8) * FC_S + ab];
        uint32_t a2 = ahi[r * FC_S + ab + 4];
        uint32_t a3 = ahi[(r + 8) * FC_S + ab + 4];
        uint32_t v0 = alo[r * FC_S + ab];
        uint32_t v1 = alo[(r + 8) * FC_S + ab];
        uint32_t v2 = alo[r * FC_S + ab + 4];
        uint32_t v3 = alo[(r + 8) * FC_S + ab + 4];
        #pragma unroll
        for (int nt = 0; nt < 2; nt++) {
            int n = cq * 16 + nt * 8 + gid;
            uint32_t bh0 = Whi[n * 128 + ks * 8 + tid];
            uint32_t bh1 = Whi[n * 128 + ks * 8 + tid + 4];
            uint32_t bl0 = Wlo[n * 128 + ks * 8 + tid];
            uint32_t bl1 = Wlo[n * 128 + ks * 8 + tid + 4];
            mma_bf16(c[nt][0], c[nt][1], c[nt][2], c[nt][3], a0, a1, a2, a3, bh0, bh1);
            mma_bf16(c[nt][0], c[nt][1], c[nt][2], c[nt][3], a0, a1, a2, a3, bl0, bl1);
            mma_bf16(c[nt][0], c[nt][1], c[nt][2], c[nt][3], v0, v1, v2, v3, bh0, bh1);
        }
    }
    #pragma unroll
    for (int nt = 0; nt < 2; nt++) {
        int col = cq * 16 + nt * 8 + tid * 2;
        float2 bbv = *(const float2*)(fcb + ty * 64 + col);
        int r0 = row0 + mt * 16 + gid;
        if (r0 < NPT) {
            int d = type_idx[ty * NPT + r0];
            *(float2*)(g_transformed + (size_t)d * 64 + col) =
                make_float2(c[nt][0] + bbv.x, c[nt][1] + bbv.y);
        }
        if (r0 + 8 < NPT) {
            int d = type_idx[ty * NPT + r0 + 8];
            *(float2*)(g_transformed + (size_t)d * 64 + col) =
                make_float2(c[nt][2] + bbv.x, c[nt][3] + bbv.y);
        }
    }
}

// ---------------- 2: gather + z = h @ gat_W via split-bf16 MMA, fused el/er ----------------
#define GA_S 36
__global__ void k_gatz(const int* __restrict__ node_idx,
                       const float* __restrict__ al, const float* __restrict__ ar) {
    __shared__ uint32_t ahi[32 * GA_S], alo[32 * GA_S];
    __shared__ float sel[32][NH], ser[32][NH];
    int g = blockIdx.y;
    int row0 = blockIdx.x * 32;
    int t = threadIdx.x;
    if (t < 128) { sel[t >> 2][t & 3] = 0.f; ser[t >> 2][t & 3] = 0.f; }
    for (int i = t; i < 32 * 32; i += 256) {
        int r = i >> 5, c = i & 31;
        int rr = row0 + r; rr = rr < NPG ? rr : NPG - 1;
        int node = node_idx[g * NPG + rr];
        float2 xv = *(const float2*)(g_transformed + (size_t)node * 64 + c * 2);
        uint32_t hp = bf2(xv.x, xv.y);
        float h0 = __uint_as_float(hp << 16);
        float h1 = __uint_as_float(hp & 0xffff0000u);
        ahi[r * GA_S + c] = hp;
        alo[r * GA_S + c] = bf2(xv.x - h0, xv.y - h1);
    }
    __syncthreads();
    int wid = t >> 5, lane = t & 31;
    int gid = lane >> 2, tid = lane & 3;
    int n0 = wid * 32;
    const uint32_t* Whi = g_gatWhi + (size_t)g * 8192;
    const uint32_t* Wlo = g_gatWlo + (size_t)g * 8192;
    float c[2][4][4] = {};
    #pragma unroll
    for (int ks = 0; ks < 4; ks++) {
        int ab = ks * 8 + tid;
        uint32_t ah[2][4], av[2][4];
        #pragma unroll
        for (int mt = 0; mt < 2; mt++) {
            int r = mt * 16 + gid;
            ah[mt][0] = ahi[r * GA_S + ab];           av[mt][0] = alo[r * GA_S + ab];
            ah[mt][1] = ahi[(r + 8) * GA_S + ab];     av[mt][1] = alo[(r + 8) * GA_S + ab];
            ah[mt][2] = ahi[r * GA_S + ab + 4];       av[mt][2] = alo[r * GA_S + ab + 4];
            ah[mt][3] = ahi[(r + 8) * GA_S + ab + 4]; av[mt][3] = alo[(r + 8) * GA_S + ab + 4];
        }
        #pragma unroll
        for (int nt = 0; nt < 4; nt++) {
            int n = n0 + nt * 8 + gid;
            uint32_t bh0 = Whi[n * 32 + ks * 8 + tid];
            uint32_t bh1 = Whi[n * 32 + ks * 8 + tid + 4];
            uint32_t bl0 = Wlo[n * 32 + ks * 8 + tid];
            uint32_t bl1 = Wlo[n * 32 + ks * 8 + tid + 4];
            #pragma unroll
            for (int mt = 0; mt < 2; mt++) {
                mma_bf16(c[mt][nt][0], c[mt][nt][1], c[mt][nt][2], c[mt][nt][3],
                         ah[mt][0], ah[mt][1], ah[mt][2], ah[mt][3], bh0, bh1);
                mma_bf16(c[mt][nt][0], c[mt][nt][1], c[mt][nt][2], c[mt][nt][3],
                         ah[mt][0], ah[mt][1], ah[mt][2], ah[mt][3], bl0, bl1);
                mma_bf16(c[mt][nt][0], c[mt][nt][1], c[mt][nt][2], c[mt][nt][3],
                         av[mt][0], av[mt][1], av[mt][2], av[mt][3], bh0, bh1);
            }
        }
    }
    float pl[2][2] = {}, pr[2][2] = {};
    #pragma unroll
    for (int mt = 0; mt < 2; mt++) {
        #pragma unroll
        for (int nt = 0; nt < 4; nt++) {
            int col = n0 + nt * 8 + tid * 2;
            float2 av2 = *(const float2*)(al + g * DD + col);
            float2 rv2 = *(const float2*)(ar + g * DD + col);
            pl[mt][0] += c[mt][nt][0] * av2.x + c[mt][nt][1] * av2.y;
            pl[mt][1] += c[mt][nt][2] * av2.x + c[mt][nt][3] * av2.y;
            pr[mt][0] += c[mt][nt][0] * rv2.x + c[mt][nt][1] * rv2.y;
            pr[mt][1] += c[mt][nt][2] * rv2.x + c[mt][nt][3] * rv2.y;
            int r0 = row0 + mt * 16 + gid;
            if (r0 < NPG)
                *(float2*)(g_z + ((size_t)g * NPG + r0) * DD + col) =
                    make_float2(c[mt][nt][0], c[mt][nt][1]);
            if (r0 + 8 < NPG)
                *(float2*)(g_z + ((size_t)g * NPG + r0 + 8) * DD + col) =
                    make_float2(c[mt][nt][2], c[mt][nt][3]);
        }
    }
    #pragma unroll
    for (int off = 1; off < 4; off <<= 1) {
        #pragma unroll
        for (int mt = 0; mt < 2; mt++) {
            #pragma unroll
            for (int rp = 0; rp < 2; rp++) {
                pl[mt][rp] += __shfl_xor_sync(~0u, pl[mt][rp], off);
                pr[mt][rp] += __shfl_xor_sync(~0u, pr[mt][rp], off);
            }
        }
    }
    if (tid == 0) {
        int h = wid >> 1;
        #pragma unroll
        for (int mt = 0; mt < 2; mt++) {
            #pragma unroll
            for (int rp = 0; rp < 2; rp++) {
                int r = mt * 16 + gid + rp * 8;
                atomicAdd(&sel[r][h], pl[mt][rp]);
                atomicAdd(&ser[r][h], pr[mt][rp]);
            }
        }
    }
    __syncthreads();
    if (t < 128) {
        int r = t >> 2, h = t & 3;
        int row = row0 + r;
        if (row < NPG) {
            g_el[((size_t)g * NPG + row) * NH + h] = sel[r][h];
            g_er[((size_t)g * NPG + row) * NH + h] = ser[r][h];
        }
    }
}

// ---------------- 3: CSR build ----------------
__global__ void k_count(const int* __restrict__ edst) {
    int i = blockIdx.x * blockDim.x + threadIdx.x;
    if (i < NG * EG) { int g = i / EG; atomicAdd(&g_cnt[g * NPG + edst[i]], 1); }
}

__global__ void k_scan() {
    int g = blockIdx.x;
    __shared__ int ssum[1024];
    int t = threadIdx.x;
    const int per = (NPG + 1023) / 1024;
    int beg = t * per, end = min(beg + per, NPG);
    int s = 0;
    for (int i = beg; i < end; i++) s += g_cnt[g * NPG + i];
    ssum[t] = s;
    __syncthreads();
    for (int off = 1; off < 1024; off <<= 1) {
        int v = (t >= off) ? ssum[t - off] : 0;
        __syncthreads();
        ssum[t] += v;
        __syncthreads();
    }
    int run = (t == 0) ? 0 : ssum[t - 1];
    for (int i = beg; i < end; i++) { g_offs[g * (NPG + 1) + i] = run; run += g_cnt[g * NPG + i]; }
    if (t == 1023) g_offs[g * (NPG + 1) + NPG] = run;
}

__global__ void k_scatter(const int* __restrict__ esrc, const int* __restrict__ edst) {
    int i = blockIdx.x * blockDim.x + threadIdx.x;
    if (i < NG * EG) {
        int g = i / EG;
        int d = edst[i];
        int pos = g_offs[g * (NPG + 1) + d] + atomicAdd(&g_cur[g * NPG + d], 1);
        g_csr[g * EG + pos] = esrc[i];
    }
}

__global__ void k_flag(const int* __restrict__ tgt) {
    int i = blockIdx.x * blockDim.x + threadIdx.x;
    if (i < NG * TT) {
        int g = i / TT;
        int d = tgt[i];
        if (atomicExch(&g_flag[g * NPG + d], 1) == 0) {
            int p = atomicAdd(&g_wcnt[g], 1);
            g_list[g * TT + p] = d;
        }
    }
}

// ---------------- 4: single-pass edge softmax + aggregation ----------------
__global__ void k_agg() {
    int g = blockIdx.y;
    int widx = blockIdx.x * 8 + (threadIdx.x >> 5);
    if (widx >= g_wcnt[g]) return;
    int lane = threadIdx.x & 31;
    int half = lane >> 4;
    int sub  = lane & 15;
    int h    = sub >> 2;
    int dst  = g_list[g * TT + widx];
    int beg = g_offs[g * (NPG + 1) + dst];
    int end = g_offs[g * (NPG + 1) + dst + 1];
    const int*   csr = g_csr + g * EG;
    const float* elg = g_el + (size_t)g * NPG * NH;
    const float* zg  = g_z + (size_t)g * NPG * DD;
    float erh = g_er[(g * NPG + dst) * NH + h];
    float acc[16] = {};
    float denom = 0.f;
    for (int i = beg + half; i < end; i += 2) {
        int src = csr[i];
        float e  = lrelu(elg[src * NH + h] + erh);
        float ex = __expf(e);
        denom += ex;
        const float4* zp = (const float4*)(zg + (size_t)src * DD + sub * 16);
        float4 a = zp[0], b = zp[1], c = zp[2], d = zp[3];
        acc[0]  += ex * a.x; acc[1]  += ex * a.y; acc[2]  += ex * a.z; acc[3]  += ex * a.w;
        acc[4]  += ex * b.x; acc[5]  += ex * b.y; acc[6]  += ex * b.z; acc[7]  += ex * b.w;
        acc[8]  += ex * c.x; acc[9]  += ex * c.y; acc[10] += ex * c.z; acc[11] += ex * c.w;
        acc[12] += ex * d.x; acc[13] += ex * d.y; acc[14] += ex * d.z; acc[15] += ex * d.w;
    }
    denom += __shfl_xor_sync(~0u, denom, 16);
    #pragma unroll
    for (int j = 0; j < 16; j++) acc[j] += __shfl_xor_sync(~0u, acc[j], 16);
    if (half == 0) {
        float inv = 1.f / (denom + 1e-9f);
        float* op = g_o + ((size_t)g * NPG + dst) * DD + sub * 16;
        float4 v[4];
        #pragma unroll
        for (int j = 0; j < 16; j++) {
            float x = acc[j] * inv;
            ((float*)v)[j] = (x > 0.f) ? x : (__expf(x) - 1.f);
        }
        #pragma unroll
        for (int j = 0; j < 4; j++) ((float4*)op)[j] = v[j];
    }
}

// ---------------- 5: semantic score via bf16 tensor cores ----------------
#define SEMX_STRIDE 132
__global__ void k_sem(const float* __restrict__ semb,
                      const float* __restrict__ semq, const int* __restrict__ tgt) {
    __shared__ uint32_t sxb[32 * SEMX_STRIDE];
    __shared__ float sred[256];
    int g = blockIdx.y, b = g >> 1;
    int row0 = blockIdx.x * 32;
    int t = threadIdx.x;
    for (int i = t; i < 32 * 128; i += 256) {
        int r = i >> 7, c = i & 127;
        int node = tgt[g * TT + row0 + r];
        float2 xv = *(const float2*)(g_o + ((size_t)g * NPG + node) * DD + c * 2);
        sxb[r * SEMX_STRIDE + c] = bf2(xv.x, xv.y);
    }
    __syncthreads();
    int wid = t >> 5, lane = t & 31;
    int gid = lane >> 2, tid = lane & 3;
    int n0 = wid * 32;
    const uint32_t* Wb = (const uint32_t*)g_semWbt + (size_t)b * 32768;
    float c[2][4][4] = {};
    for (int ks = 0; ks < 16; ks++) {
        int abase = ks * 8 + tid;
        uint32_t a[2][4];
        #pragma unroll
        for (int mt = 0; mt < 2; mt++) {
            int r = mt * 16 + gid;
            a[mt][0] = sxb[r * SEMX_STRIDE + abase];
            a[mt][1] = sxb[(r + 8) * SEMX_STRIDE + abase];
            a[mt][2] = sxb[r * SEMX_STRIDE + abase + 4];
            a[mt][3] = sxb[(r + 8) * SEMX_STRIDE + abase + 4];
        }
        #pragma unroll
        for (int nt = 0; nt < 4; nt++) {
            int n = n0 + nt * 8 + gid;
            uint32_t b0 = Wb[n * 128 + ks * 8 + tid];
            uint32_t b1 = Wb[n * 128 + ks * 8 + tid + 4];
            #pragma unroll
            for (int mt = 0; mt < 2; mt++)
                mma_bf16(c[mt][nt][0], c[mt][nt][1], c[mt][nt][2], c[mt][nt][3],
                         a[mt][0], a[mt][1], a[mt][2], a[mt][3], b0, b1);
        }
    }
    float part = 0.f;
    #pragma unroll
    for (int nt = 0; nt < 4; nt++) {
        int col = n0 + nt * 8 + tid * 2;
        float2 bbv = *(const float2*)(semb + b * DD + col);
        float2 qqv = *(const float2*)(semq + b * DD + col);
        #pragma unroll
        for (int mt = 0; mt < 2; mt++) {
            part += tanh_fast(c[mt][nt][0] + bbv.x) * qqv.x;
            part += tanh_fast(c[mt][nt][1] + bbv.y) * qqv.y;
            part += tanh_fast(c[mt][nt][2] + bbv.x) * qqv.x;
            part += tanh_fast(c[mt][nt][3] + bbv.y) * qqv.y;
        }
    }
    sred[t] = part;
    __syncthreads();
    for (int s2 = 128; s2; s2 >>= 1) {
        if (t < s2) sred[t] += sred[t + s2];
        __syncthreads();
    }
    if (t == 0) atomicAdd(&g_wsum[g], sred[0]);
}

__global__ void k_beta() {
    if (threadIdx.x == 0 && blockIdx.x == 0) {
        for (int b = 0; b < 2; b++) {
            float w0 = g_wsum[b * 2 + 0] / (float)TT;
            float w1 = g_wsum[b * 2 + 1] / (float)TT;
            float mx = fmaxf(w0, w1);
            float e0 = __expf(w0 - mx), e1 = __expf(w1 - mx);
            float s = e0 + e1;
            g_beta[b * 2 + 0] = e0 / s;
            g_beta[b * 2 + 1] = e1 / s;
        }
    }
}

// ---------------- 6: beta-mix + fcout (32 rows/block, 256 thr) ----------------
#define OUT_PAD 34
__global__ void k_out(const float* __restrict__ foW, const float* __restrict__ fob,
                      const int* __restrict__ tgt, float* __restrict__ out) {
    int b = blockIdx.y;
    int row0 = blockIdx.x * 32;
    __shared__ float sx[256 * OUT_PAD];
    int t = threadIdx.x;
    float b0 = g_beta[b * 2], b1 = g_beta[b * 2 + 1];
    for (int i = t; i < 32 * 256; i += 256) {
        int r = i >> 8, k = i & 255;
        int row = row0 + r;
        int n0 = tgt[(b * 2 + 0) * TT + row];
        int n1 = tgt[(b * 2 + 1) * TT + row];
        sx[k * OUT_PAD + r] = b0 * g_o[((size_t)(b * 2 + 0) * NPG + n0) * DD + k]
                            + b1 * g_o[((size_t)(b * 2 + 1) * NPG + n1) * DD + k];
    }
    __syncthreads();
    int oq = t & 15, rg = t >> 4;
    const float* W = foW + (size_t)b * DD * OUTD;
    u64 acc0 = 0, acc1 = 0, acc2 = 0, acc3 = 0;
    #pragma unroll 4
    for (int k = 0; k < 256; k++) {
        float4 w = *(const float4*)(W + k * 64 + oq * 4);
        u64 xp = *(const u64*)&sx[k * OUT_PAD + rg * 2];
        u64 w0, w1, w2, w3;
        asm("mov.b64 %0, {%1, %1};" : "=l"(w0) : "f"(w.x));
        asm("mov.b64 %0, {%1, %1};" : "=l"(w1) : "f"(w.y));
        asm("mov.b64 %0, {%1, %1};" : "=l"(w2) : "f"(w.z));
        asm("mov.b64 %0, {%1, %1};" : "=l"(w3) : "f"(w.w));
        fma2(acc0, w0, xp); fma2(acc1, w1, xp);
        fma2(acc2, w2, xp); fma2(acc3, w3, xp);
    }
    float4 bb = *(const float4*)(fob + b * 64 + oq * 4);
    float2 a0 = unpack2(acc0), a1 = unpack2(acc1), a2 = unpack2(acc2), a3 = unpack2(acc3);
    int r0 = row0 + rg * 2;
    *(float4*)(out + ((size_t)b * TT + r0) * OUTD + oq * 4) =
        make_float4(a0.x + bb.x, a1.x + bb.y, a2.x + bb.z, a3.x + bb.w);
    *(float4*)(out + ((size_t)b * TT + r0 + 1) * OUTD + oq * 4) =
        make_float4(a0.y + bb.x, a1.y + bb.y, a2.y + bb.z, a3.y + bb.w);
}

// ---------------- launch ----------------
extern "C" void kernel_launch(void* const* d_in, const int* in_sizes, int n_in,
                              void* d_out, int out_size) {
    const float* features0 = (const float*)d_in[0];
    const float* features1 = (const float*)d_in[1];
    const float* fc_W      = (const float*)d_in[2];
    const float* fc_b      = (const float*)d_in[3];
    const float* gat_W     = (const float*)d_in[4];
    const float* attn_l    = (const float*)d_in[5];
    const float* attn_r    = (const float*)d_in[6];
    const float* sem_W     = (const float*)d_in[7];
    const float* sem_b     = (const float*)d_in[8];
    const float* sem_q     = (const float*)d_in[9];
    const float* fcout_W   = (const float*)d_in[10];
    const float* fcout_b   = (const float*)d_in[11];
    const int*   type_idx  = (const int*)d_in[12];
    const int*   node_idx  = (const int*)d_in[13];
    const int*   edge_src  = (const int*)d_in[14];
    const int*   edge_dst  = (const int*)d_in[15];
    const int*   tgt_idx   = (const int*)d_in[16];
    float* out = (float*)d_out;

    k_tw<<<768, 256>>>(fc_W, sem_W, gat_W);                     // 1
    k_zero<<<(NG * NPG + 255) / 256, 256>>>();                  // 2
    {
        dim3 grid((NPT + 31) / 32, 2);
        k_fc<<<grid, 256>>>(features0, features1, fc_b, type_idx);  // 3
    }
    {
        dim3 grid((NPG + 31) / 32, NG);
        k_gatz<<<grid, 256>>>(node_idx, attn_l, attn_r);        // 4 <- ncu capture slot
    }
    k_count<<<(NG * EG + 255) / 256, 256>>>(edge_dst);
    k_scan<<<NG, 1024>>>();
    k_scatter<<<(NG * EG + 255) / 256, 256>>>(edge_src, edge_dst);
    k_flag<<<(NG * TT + 255) / 256, 256>>>(tgt_idx);
    {
        dim3 grid((TT + 7) / 8, NG);
        k_agg<<<grid, 256>>>();
    }
    {
        dim3 grid(TT / 32, NG);
        k_sem<<<grid, 256>>>(sem_b, sem_q, tgt_idx);
    }
    k_beta<<<1, 32>>>();
    {
        dim3 grid(TT / 32, 2);
        k_out<<<grid, 256>>>(fcout_W, fcout_b, tgt_idx, out);
    }
}